// round 12
// baseline (speedup 1.0000x reference)
#include <cuda_runtime.h>
#include <cuda_bf16.h>
#include <math.h>
#include <stdint.h>

#define D 128
static constexpr int MAXN = 51200;
static constexpr int MAXMATS = 16;   // slots; last used slot holds Wg frags

// ---------------------------------------------------------------------------
// Scratch (no allocs allowed -> device globals)
// ---------------------------------------------------------------------------
__device__ float d_mj[MAXN * D];
__device__ float d_v [MAXN * D];
__device__ __align__(16) uint32_t d_wimg[MAXMATS * 16384];

__device__ __forceinline__ float sspf(float x) {
    return fmaxf(x, 0.0f) + __logf(1.0f + __expf(-fabsf(x))) - 0.69314718055994530942f;
}

// ---------------------------------------------------------------------------
// HMMA m16n8k16 bf16 (base PTX) + frag building
// ---------------------------------------------------------------------------
__device__ __forceinline__ void mma_bf16(float* d, const uint32_t* a,
                                         uint32_t b0, uint32_t b1) {
    asm volatile(
        "mma.sync.aligned.m16n8k16.row.col.f32.bf16.bf16.f32 "
        "{%0,%1,%2,%3}, {%4,%5,%6,%7}, {%8,%9}, {%0,%1,%2,%3};"
        : "+f"(d[0]), "+f"(d[1]), "+f"(d[2]), "+f"(d[3])
        : "r"(a[0]), "r"(a[1]), "r"(a[2]), "r"(a[3]), "r"(b0), "r"(b1));
}

__device__ __forceinline__ void build_frag(float s0, float s1,
                                           uint32_t& hi, uint32_t& lo) {
    __nv_bfloat162 h2 = __floats2bfloat162_rn(s0, s1);
    float l0 = s0 - __bfloat162float(h2.x);
    float l1 = s1 - __bfloat162float(h2.y);
    __nv_bfloat162 l2 = __floats2bfloat162_rn(l0, l1);
    hi = *reinterpret_cast<uint32_t*>(&h2);
    lo = *reinterpret_cast<uint32_t*>(&l2);
}

// ---------------------------------------------------------------------------
// cp.async helpers
// ---------------------------------------------------------------------------
__device__ __forceinline__ uint32_t smem_u32(const void* p) {
    uint32_t a;
    asm("{ .reg .u64 t; cvta.to.shared.u64 t, %1; cvt.u32.u64 %0, t; }"
        : "=r"(a) : "l"(p));
    return a;
}
#define CP_ASYNC16(dst, src) \
    asm volatile("cp.async.cg.shared.global [%0], [%1], 16;" :: "r"(dst), "l"(src))
#define CP_COMMIT() asm volatile("cp.async.commit_group;" ::: "memory")
#define CP_WAIT1()  asm volatile("cp.async.wait_group 1;"  ::: "memory")

// ---------------------------------------------------------------------------
// Weight precompute (8 blocks per matrix)
// ---------------------------------------------------------------------------
__global__ void wsplit_kernel(const float* __restrict__ Wj,
                              const float* __restrict__ Wi,
                              const float* __restrict__ Wf,
                              const float* __restrict__ rWint,
                              const float* __restrict__ rWatm,
                              const float* __restrict__ rWout,
                              const float* __restrict__ Wg,
                              int n_int, int n_atom, int n_out) {
    int m    = blockIdx.x >> 3;
    int part = blockIdx.x & 7;
    int n_mats = 3 + n_int + n_atom + n_out;

    if (m == n_mats) {  // Wg [32 x 128]
        uint32_t* hi = d_wimg + (size_t)m * 16384;
        uint32_t* lo = hi + 2048;
        for (int idx = part * 256 + threadIdx.x; idx < 2048; idx += 2048) {
            int ri = idx & 1;
            int l  = (idx >> 1) & 31;
            int f  = idx >> 6;
            int kt = f & 1, nt = f >> 1;
            int n  = nt * 8 + (l >> 2);
            int k0 = kt * 16 + 2 * (l & 3) + ri * 8;
            uint32_t h, lw;
            build_frag(Wg[k0 * D + n], Wg[(k0 + 1) * D + n], h, lw);
            hi[idx] = h;
            lo[idx] = lw;
        }
        return;
    }

    const float* src;
    if (m == 0)                      src = Wj;
    else if (m == 1)                 src = Wi;
    else if (m == 2)                 src = Wf;
    else if (m < 3 + n_int)          src = rWint + (size_t)(m - 3) * D * D;
    else if (m < 3 + n_int + n_atom) src = rWatm + (size_t)(m - 3 - n_int) * D * D;
    else                             src = rWout + (size_t)(m - 3 - n_int - n_atom) * D * D;

    uint32_t* hi = d_wimg + (size_t)m * 16384;
    uint32_t* lo = hi + 8192;

    for (int idx = part * 1024 + threadIdx.x; idx < (part + 1) * 1024; idx += 256) {
        int ri = idx & 1;
        int l  = (idx >> 1) & 31;
        int f  = idx >> 6;
        int kt = f & 7, nt = f >> 3;
        int n  = nt * 8 + (l >> 2);
        int k0 = kt * 16 + 2 * (l & 3) + ri * 8;
        uint32_t h, lw;
        build_frag(src[k0 * D + n], src[(k0 + 1) * D + n], h, lw);
        hi[idx] = h;
        lo[idx] = lw;
    }
}

// ---------------------------------------------------------------------------
// MMA stage with B in smem (head kernel): pass-separated, 4-nt chunks.
// ---------------------------------------------------------------------------
__device__ __forceinline__ void stage_mma_smem(const uint32_t* wsm, int loff,
                                               const uint32_t* ahi, const uint32_t* alo,
                                               float* acc) {
    const char* base = reinterpret_cast<const char*>(wsm);
    #pragma unroll
    for (int kt = 0; kt < 8; kt++) {
        #pragma unroll
        for (int c = 0; c < 4; c++) {
            uint2 bh[4], bl[4];
            #pragma unroll
            for (int i = 0; i < 4; i++)
                bh[i] = *reinterpret_cast<const uint2*>(base + ((c * 4 + i) * 8 + kt) * 256 + loff);
            #pragma unroll
            for (int i = 0; i < 4; i++)
                bl[i] = *reinterpret_cast<const uint2*>(base + 32768 + ((c * 4 + i) * 8 + kt) * 256 + loff);
            #pragma unroll
            for (int i = 0; i < 4; i++)
                mma_bf16(acc + (c * 4 + i) * 4, ahi + kt * 4, bh[i].x, bh[i].y);
            #pragma unroll
            for (int i = 0; i < 4; i++)
                mma_bf16(acc + (c * 4 + i) * 4, alo + kt * 4, bh[i].x, bh[i].y);
            #pragma unroll
            for (int i = 0; i < 4; i++)
                mma_bf16(acc + (c * 4 + i) * 4, ahi + kt * 4, bl[i].x, bl[i].y);
        }
    }
}

// ---------------------------------------------------------------------------
// Head kernel: A = ssp(x); mj = ssp(A@Wj+bj); v = ssp(A@Wi+bi)
// ---------------------------------------------------------------------------
static constexpr int HEAD_SMEM = (16384 + 128) * 4;

__global__ void __launch_bounds__(256, 1)
tc_head_kernel(const float* __restrict__ x,
               const float* __restrict__ bj, const float* __restrict__ bi,
               float* __restrict__ mj, float* __restrict__ v, int N) {
    extern __shared__ uint32_t sm[];
    float* bias_s = reinterpret_cast<float*>(sm + 16384);

    const int t = threadIdx.x, w = t >> 5, l = t & 31;
    const int g = l >> 2, m4 = l & 3;
    const int loff = l * 8;
    const int row_lo = blockIdx.x * 128 + w * 16 + g;
    const int row_hi = row_lo + 8;
    const int cb = 2 * m4;

    uint32_t ahi[32], alo[32];
    #pragma unroll
    for (int nt = 0; nt < 16; nt++) {
        int c0 = nt * 8 + cb;
        float2 a = (row_lo < N) ? *reinterpret_cast<const float2*>(x + (size_t)row_lo * D + c0)
                                : make_float2(0.f, 0.f);
        float2 b = (row_hi < N) ? *reinterpret_cast<const float2*>(x + (size_t)row_hi * D + c0)
                                : make_float2(0.f, 0.f);
        int base = (nt >> 1) * 4 + (nt & 1) * 2;
        build_frag(sspf(a.x), sspf(a.y), ahi[base], alo[base]);
        build_frag(sspf(b.x), sspf(b.y), ahi[base + 1], alo[base + 1]);
    }

    for (int s = 0; s < 2; s++) {
        __syncthreads();
        const uint4* src = reinterpret_cast<const uint4*>(d_wimg + (size_t)s * 16384);
        uint4* dst = reinterpret_cast<uint4*>(sm);
        #pragma unroll
        for (int i = 0; i < 16; i++)
            dst[t + 256 * i] = src[t + 256 * i];
        if (t < 32)
            reinterpret_cast<float4*>(bias_s)[t] =
                reinterpret_cast<const float4*>(s ? bi : bj)[t];
        __syncthreads();

        float acc[64];
        #pragma unroll
        for (int i = 0; i < 64; i++) acc[i] = 0.0f;
        stage_mma_smem(sm, loff, ahi, alo, acc);

        float* outp = s ? v : mj;
        #pragma unroll
        for (int nt = 0; nt < 16; nt++) {
            int c0 = nt * 8 + cb;
            float bv0 = bias_s[c0], bv1 = bias_s[c0 + 1];
            float s0 = sspf(acc[nt * 4 + 0] + bv0);
            float s1 = sspf(acc[nt * 4 + 1] + bv1);
            float s2 = sspf(acc[nt * 4 + 2] + bv0);
            float s3 = sspf(acc[nt * 4 + 3] + bv1);
            if (row_lo < N)
                *reinterpret_cast<float2*>(outp + (size_t)row_lo * D + c0) = make_float2(s0, s1);
            if (row_hi < N)
                *reinterpret_cast<float2*>(outp + (size_t)row_hi * D + c0) = make_float2(s2, s3);
        }
    }
}

// ---------------------------------------------------------------------------
// Tail kernel: register-chained, cp.async double-buffered weights,
// CHUNK-INTERLEAVED: per 4-nt chunk, MMA then immediate epilogue, so one
// chunk's MUFU/FMA epilogue overlaps the next chunk's LDS/HMMA.
// ---------------------------------------------------------------------------
static constexpr int BUFW = 16512;
static constexpr int TAIL_SMEM = (2 * BUFW + 128) * 4;

__device__ __forceinline__ void issue_stage_copy(uint32_t buf_addr,
                                                 const uint32_t* img,
                                                 const float* bias, int t) {
    #pragma unroll
    for (int i = 0; i < 16; i++)
        CP_ASYNC16(buf_addr + (t + 256 * i) * 16, img + (t + 256 * i) * 4);
    if (t < 32)
        CP_ASYNC16(buf_addr + 16384 * 4 + t * 16, bias + t * 4);
}

__global__ void __launch_bounds__(256, 1)
tc_tail_kernel(const float* __restrict__ v_in, const float* __restrict__ x,
               const float* __restrict__ u,
               const float* __restrict__ rbint, const float* __restrict__ bf,
               const float* __restrict__ rbatm, const float* __restrict__ rbout,
               int n_int, int n_atom, int n_out,
               float* __restrict__ h_out, float* __restrict__ o_out, int N) {
    extern __shared__ uint32_t sm[];
    float* u_s = reinterpret_cast<float*>(sm + 2 * BUFW);
    const uint32_t sm_addr = smem_u32(sm);

    const int t = threadIdx.x, w = t >> 5, l = t & 31;
    const int g = l >> 2, m4 = l & 3;
    const int loff = l * 8;
    const int row_lo = blockIdx.x * 128 + w * 16 + g;
    const int row_hi = row_lo + 8;
    const int cb = 2 * m4;

    if (t < 32)
        reinterpret_cast<float4*>(u_s)[t] = reinterpret_cast<const float4*>(u)[t];

    const int total = 2 * n_int + 1 + 2 * n_atom + 2 * n_out;

    auto stage_desc = [&](int s, int& mat, const float*& bias, int& mode, bool& storeh) {
        storeh = false;
        if (s < 2 * n_int) {
            mat = 3 + (s >> 1); bias = rbint + (size_t)(s >> 1) * D;
            mode = (s & 1) ? 1 : 0;
        } else if (s == 2 * n_int) {
            mat = 2; bias = bf; mode = 2; storeh = (n_atom == 0);
        } else {
            int s2 = s - 2 * n_int - 1;
            if (s2 < 2 * n_atom) {
                mat = 3 + n_int + (s2 >> 1); bias = rbatm + (size_t)(s2 >> 1) * D;
                mode = (s2 & 1) ? 1 : 0;
                storeh = (s2 == 2 * n_atom - 1);
            } else {
                int s3 = s2 - 2 * n_atom;
                mat = 3 + n_int + n_atom + (s3 >> 1); bias = rbout + (size_t)(s3 >> 1) * D;
                mode = (s3 & 1) ? ((s3 == 2 * n_out - 1) ? 3 : 1) : 0;
            }
        }
    };

    {
        int mat; const float* bias; int mode; bool sh;
        stage_desc(0, mat, bias, mode, sh);
        issue_stage_copy(sm_addr, d_wimg + (size_t)mat * 16384, bias, t);
        CP_COMMIT();
    }

    float vr[64];
    uint32_t ahi[32], alo[32];
    #pragma unroll
    for (int nt = 0; nt < 16; nt++) {
        int c0 = nt * 8 + cb;
        float2 a = (row_lo < N) ? *reinterpret_cast<const float2*>(v_in + (size_t)row_lo * D + c0)
                                : make_float2(0.f, 0.f);
        float2 b = (row_hi < N) ? *reinterpret_cast<const float2*>(v_in + (size_t)row_hi * D + c0)
                                : make_float2(0.f, 0.f);
        vr[nt * 4 + 0] = a.x; vr[nt * 4 + 1] = a.y;
        vr[nt * 4 + 2] = b.x; vr[nt * 4 + 3] = b.y;
        int base = (nt >> 1) * 4 + (nt & 1) * 2;
        build_frag(sspf(a.x), sspf(a.y), ahi[base], alo[base]);
        build_frag(sspf(b.x), sspf(b.y), ahi[base + 1], alo[base + 1]);
    }

    for (int s = 0; s < total; s++) {
        int mat; const float* bias; int mode; bool storeh;
        stage_desc(s, mat, bias, mode, storeh);

        if (s + 1 < total) {
            int nmat; const float* nbias; int nmode; bool nsh;
            stage_desc(s + 1, nmat, nbias, nmode, nsh);
            issue_stage_copy(sm_addr + ((s + 1) & 1) * BUFW * 4,
                             d_wimg + (size_t)nmat * 16384, nbias, t);
        }
        CP_COMMIT();
        CP_WAIT1();
        __syncthreads();

        const uint32_t* wbuf = sm + (s & 1) * BUFW;
        const float* bias_s = reinterpret_cast<const float*>(wbuf + 16384);
        const char* base = reinterpret_cast<const char*>(wbuf);

        uint32_t nhi[32], nlo[32];

        #pragma unroll
        for (int c = 0; c < 4; c++) {
            // ---- MMA for nt chunk c (nt = 4c .. 4c+3) ----
            float acc[16];
            #pragma unroll
            for (int i = 0; i < 16; i++) acc[i] = 0.0f;
            #pragma unroll
            for (int kt = 0; kt < 8; kt++) {
                uint2 bh[4], bl[4];
                #pragma unroll
                for (int i = 0; i < 4; i++)
                    bh[i] = *reinterpret_cast<const uint2*>(
                        base + ((c * 4 + i) * 8 + kt) * 256 + loff);
                #pragma unroll
                for (int i = 0; i < 4; i++)
                    bl[i] = *reinterpret_cast<const uint2*>(
                        base + 32768 + ((c * 4 + i) * 8 + kt) * 256 + loff);
                #pragma unroll
                for (int i = 0; i < 4; i++)
                    mma_bf16(acc + i * 4, ahi + kt * 4, bh[i].x, bh[i].y);
                #pragma unroll
                for (int i = 0; i < 4; i++)
                    mma_bf16(acc + i * 4, alo + kt * 4, bh[i].x, bh[i].y);
                #pragma unroll
                for (int i = 0; i < 4; i++)
                    mma_bf16(acc + i * 4, ahi + kt * 4, bl[i].x, bl[i].y);
            }

            // ---- immediate epilogue for chunk c ----
            #pragma unroll
            for (int i = 0; i < 4; i++) {
                int nt = c * 4 + i;
                int c0 = nt * 8 + cb;
                float bv0 = bias_s[c0], bv1 = bias_s[c0 + 1];
                float v0 = acc[i * 4 + 0] + bv0;
                float v1 = acc[i * 4 + 1] + bv1;
                float v2 = acc[i * 4 + 2] + bv0;
                float v3 = acc[i * 4 + 3] + bv1;
                if (mode == 1 || mode == 3) {
                    v0 += vr[nt * 4 + 0]; v1 += vr[nt * 4 + 1];
                    v2 += vr[nt * 4 + 2]; v3 += vr[nt * 4 + 3];
                }
                if (mode == 2) {
                    float2 xl = (row_lo < N) ? *reinterpret_cast<const float2*>(x + (size_t)row_lo * D + c0)
                                             : make_float2(0.f, 0.f);
                    float2 xh = (row_hi < N) ? *reinterpret_cast<const float2*>(x + (size_t)row_hi * D + c0)
                                             : make_float2(0.f, 0.f);
                    float u0 = u_s[c0], u1 = u_s[c0 + 1];
                    v0 += u0 * sspf(xl.x); v1 += u1 * sspf(xl.y);
                    v2 += u0 * sspf(xh.x); v3 += u1 * sspf(xh.y);
                }
                if (mode == 1 || mode == 2) {
                    vr[nt * 4 + 0] = v0; vr[nt * 4 + 1] = v1;
                    vr[nt * 4 + 2] = v2; vr[nt * 4 + 3] = v3;
                }
                float s0 = sspf(v0), s1 = sspf(v1), s2 = sspf(v2), s3 = sspf(v3);
                if (mode == 3) {
                    if (row_lo < N)
                        *reinterpret_cast<float2*>(o_out + (size_t)row_lo * D + c0) = make_float2(s0, s1);
                    if (row_hi < N)
                        *reinterpret_cast<float2*>(o_out + (size_t)row_hi * D + c0) = make_float2(s2, s3);
                } else {
                    int fb = (nt >> 1) * 4 + (nt & 1) * 2;
                    build_frag(s0, s1, nhi[fb], nlo[fb]);
                    build_frag(s2, s3, nhi[fb + 1], nlo[fb + 1]);
                }
            }
        }

        if (mode != 3) {
            #pragma unroll
            for (int i = 0; i < 32; i++) { ahi[i] = nhi[i]; alo[i] = nlo[i]; }
        }

        if (storeh) {
            #pragma unroll
            for (int nt = 0; nt < 16; nt++) {
                int c0 = nt * 8 + cb;
                if (row_lo < N)
                    *reinterpret_cast<float2*>(h_out + (size_t)row_lo * D + c0) =
                        make_float2(vr[nt * 4 + 0], vr[nt * 4 + 1]);
                if (row_hi < N)
                    *reinterpret_cast<float2*>(h_out + (size_t)row_hi * D + c0) =
                        make_float2(vr[nt * 4 + 2], vr[nt * 4 + 3]);
            }
        }
        __syncthreads();
    }
}

// ---------------------------------------------------------------------------
// Edge kernel (R6 proven): HMMA gate + packed red.v4 scatter.
// ---------------------------------------------------------------------------
__global__ __launch_bounds__(256)
void edge_mma_kernel(const float* __restrict__ g,
                     const int* __restrict__ idx_i,
                     const int* __restrict__ idx_j,
                     const float* __restrict__ mj,
                     float* __restrict__ v,
                     int E, int wg_slot) {
    __shared__ uint32_t wgs[4096];
    {
        const uint4* src = reinterpret_cast<const uint4*>(d_wimg + (size_t)wg_slot * 16384);
        uint4* dst = reinterpret_cast<uint4*>(wgs);
        #pragma unroll
        for (int i = threadIdx.x; i < 1024; i += 256)
            dst[i] = src[i];
    }
    __syncthreads();

    const int t = threadIdx.x, l = t & 31;
    const int gq = l >> 2, m4 = l & 3;
    const int batch = blockIdx.x * 8 + (t >> 5);
    const int e0 = batch * 16;
    if (e0 >= E) return;

    const int r0 = e0 + gq, r1 = r0 + 8;
    const bool v0ok = (r0 < E), v1ok = (r1 < E);
    const int j0 = v0ok ? __ldg(idx_j + r0) : 0;
    const int i0 = v0ok ? __ldg(idx_i + r0) : 0;
    const int j1 = v1ok ? __ldg(idx_j + r1) : 0;
    const int i1 = v1ok ? __ldg(idx_i + r1) : 0;

    uint32_t ahi[8], alo[8];
    #pragma unroll
    for (int kt = 0; kt < 2; kt++) {
        int kb = kt * 16 + 2 * m4;
        float2 p00 = v0ok ? *reinterpret_cast<const float2*>(g + (size_t)r0 * 32 + kb)
                          : make_float2(0.f, 0.f);
        float2 p01 = v0ok ? *reinterpret_cast<const float2*>(g + (size_t)r0 * 32 + kb + 8)
                          : make_float2(0.f, 0.f);
        float2 p10 = v1ok ? *reinterpret_cast<const float2*>(g + (size_t)r1 * 32 + kb)
                          : make_float2(0.f, 0.f);
        float2 p11 = v1ok ? *reinterpret_cast<const float2*>(g + (size_t)r1 * 32 + kb + 8)
                          : make_float2(0.f, 0.f);
        build_frag(p00.x, p00.y, ahi[kt * 4 + 0], alo[kt * 4 + 0]);
        build_frag(p10.x, p10.y, ahi[kt * 4 + 1], alo[kt * 4 + 1]);
        build_frag(p01.x, p01.y, ahi[kt * 4 + 2], alo[kt * 4 + 2]);
        build_frag(p11.x, p11.y, ahi[kt * 4 + 3], alo[kt * 4 + 3]);
    }

    float acc[64];
    #pragma unroll
    for (int i = 0; i < 64; i++) acc[i] = 0.0f;

    const char* base = reinterpret_cast<const char*>(wgs);
    const int loff = l * 8;
    #pragma unroll
    for (int nt = 0; nt < 16; nt++) {
        #pragma unroll
        for (int kt = 0; kt < 2; kt++) {
            uint2 bh = *reinterpret_cast<const uint2*>(base + (nt * 2 + kt) * 256 + loff);
            mma_bf16(acc + nt * 4, ahi + kt * 4, bh.x, bh.y);
            mma_bf16(acc + nt * 4, alo + kt * 4, bh.x, bh.y);
            uint2 bl = *reinterpret_cast<const uint2*>(base + 8192 + (nt * 2 + kt) * 256 + loff);
            mma_bf16(acc + nt * 4, ahi + kt * 4, bl.x, bl.y);
        }
    }

    const bool evenlane = ((l & 1) == 0);
    #pragma unroll
    for (int nt = 0; nt < 16; nt++) {
        int c0 = nt * 8 + 2 * m4;
        float p0 = 0.f, p1 = 0.f, p2 = 0.f, p3 = 0.f;
        if (v0ok) {
            float2 m0 = *reinterpret_cast<const float2*>(mj + (size_t)j0 * D + c0);
            p0 = acc[nt * 4 + 0] * m0.x;
            p1 = acc[nt * 4 + 1] * m0.y;
        }
        if (v1ok) {
            float2 m1 = *reinterpret_cast<const float2*>(mj + (size_t)j1 * D + c0);
            p2 = acc[nt * 4 + 2] * m1.x;
            p3 = acc[nt * 4 + 3] * m1.y;
        }
        float q0 = __shfl_xor_sync(0xffffffffu, p0, 1);
        float q1 = __shfl_xor_sync(0xffffffffu, p1, 1);
        float q2 = __shfl_xor_sync(0xffffffffu, p2, 1);
        float q3 = __shfl_xor_sync(0xffffffffu, p3, 1);
        if (evenlane) {
            if (v0ok)
                asm volatile("red.global.add.v4.f32 [%0], {%1, %2, %3, %4};"
                             :: "l"(v + (size_t)i0 * D + c0), "f"(p0), "f"(p1), "f"(q0), "f"(q1)
                             : "memory");
            if (v1ok)
                asm volatile("red.global.add.v4.f32 [%0], {%1, %2, %3, %4};"
                             :: "l"(v + (size_t)i1 * D + c0), "f"(p2), "f"(p3), "f"(q2), "f"(q3)
                             : "memory");
        }
    }
}

// ---------------------------------------------------------------------------
// Host-side dispatch
// ---------------------------------------------------------------------------
extern "C" void kernel_launch(void* const* d_in, const int* in_sizes, int n_in,
                              void* d_out, int out_size) {
    const float* x     = (const float*)d_in[0];
    const float* g_ij  = (const float*)d_in[1];
    const float* Wf    = (const float*)d_in[2];
    const float* bf    = (const float*)d_in[3];
    const float* Wg    = (const float*)d_in[4];
    const float* Wj    = (const float*)d_in[5];
    const float* bj    = (const float*)d_in[6];
    const float* Wi    = (const float*)d_in[7];
    const float* bi    = (const float*)d_in[8];
    const float* u     = (const float*)d_in[9];
    const float* rWint = (const float*)d_in[10];
    const float* rbint = (const float*)d_in[11];
    const float* rWatm = (const float*)d_in[12];
    const float* rbatm = (const float*)d_in[13];
    const float* rWout = (const float*)d_in[14];
    const float* rbout = (const float*)d_in[15];
    const int*   idx_i = (const int*)d_in[16];
    const int*   idx_j = (const int*)d_in[17];

    const int N      = in_sizes[0] / D;
    const int E      = in_sizes[16];
    const int n_int  = in_sizes[11] / D;
    const int n_atom = in_sizes[13] / D;
    const int n_out  = in_sizes[15] / D;

    if (N > MAXN) return;
    const int n_mats = 3 + n_int + n_atom + n_out;
    if (n_mats + 1 > MAXMATS) return;

    float *mj, *v;
    cudaGetSymbolAddress((void**)&mj, d_mj);
    cudaGetSymbolAddress((void**)&v,  d_v);

    float* o_out = (float*)d_out;                 // o -> first N*D
    float* h_out = (float*)d_out + (size_t)N * D; // h -> second N*D

    cudaFuncSetAttribute(tc_head_kernel, cudaFuncAttributeMaxDynamicSharedMemorySize, HEAD_SMEM);
    cudaFuncSetAttribute(tc_tail_kernel, cudaFuncAttributeMaxDynamicSharedMemorySize, TAIL_SMEM);

    const int tiles = (N + 127) / 128;

    // 0) split + permute weights (incl. Wg at slot n_mats)
    wsplit_kernel<<<(n_mats + 1) * 8, 256>>>(Wj, Wi, Wf, rWint, rWatm, rWout, Wg,
                                             n_int, n_atom, n_out);

    // 1) mj = ssp(ssp(x)@Wj+bj); v = ssp(ssp(x)@Wi+bi)
    tc_head_kernel<<<tiles, 256, HEAD_SMEM>>>(x, bj, bi, mj, v, N);

    // 2) v += segment_sum( (g_ij @ Wg) * mj[idx_j], idx_i )   [HMMA gate]
    {
        int batches = (E + 15) / 16;
        int blocks  = (batches + 7) / 8;
        edge_mma_kernel<<<blocks, 256>>>(g_ij, idx_i, idx_j, mj, v, E, n_mats);
    }

    // 3) fused register-chained tail, chunk-interleaved MMA/epilogue
    tc_tail_kernel<<<tiles, 256, TAIL_SMEM>>>(
        v, x, u, rbint, bf, rbatm, rbout, n_int, n_atom, n_out, h_out, o_out, N);
}

// round 13
// speedup vs baseline: 1.0774x; 1.0774x over previous
#include <cuda_runtime.h>
#include <cuda_bf16.h>
#include <math.h>
#include <stdint.h>

#define D 128
static constexpr int MAXN = 51200;
static constexpr int MAXMATS = 16;   // slots; last used slot holds Wg frags

// ---------------------------------------------------------------------------
// Scratch (no allocs allowed -> device globals)
// ---------------------------------------------------------------------------
__device__ float d_mj[MAXN * D];
__device__ float d_v [MAXN * D];
__device__ __align__(16) uint32_t d_wimg[MAXMATS * 16384];

__device__ __forceinline__ float sspf(float x) {
    return fmaxf(x, 0.0f) + __logf(1.0f + __expf(-fabsf(x))) - 0.69314718055994530942f;
}

// ---------------------------------------------------------------------------
// HMMA m16n8k16 bf16 (base PTX) + frag building
// ---------------------------------------------------------------------------
__device__ __forceinline__ void mma_bf16(float* d, const uint32_t* a,
                                         uint32_t b0, uint32_t b1) {
    asm volatile(
        "mma.sync.aligned.m16n8k16.row.col.f32.bf16.bf16.f32 "
        "{%0,%1,%2,%3}, {%4,%5,%6,%7}, {%8,%9}, {%0,%1,%2,%3};"
        : "+f"(d[0]), "+f"(d[1]), "+f"(d[2]), "+f"(d[3])
        : "r"(a[0]), "r"(a[1]), "r"(a[2]), "r"(a[3]), "r"(b0), "r"(b1));
}

__device__ __forceinline__ void build_frag(float s0, float s1,
                                           uint32_t& hi, uint32_t& lo) {
    __nv_bfloat162 h2 = __floats2bfloat162_rn(s0, s1);
    float l0 = s0 - __bfloat162float(h2.x);
    float l1 = s1 - __bfloat162float(h2.y);
    __nv_bfloat162 l2 = __floats2bfloat162_rn(l0, l1);
    hi = *reinterpret_cast<uint32_t*>(&h2);
    lo = *reinterpret_cast<uint32_t*>(&l2);
}

// ---------------------------------------------------------------------------
// cp.async helpers
// ---------------------------------------------------------------------------
__device__ __forceinline__ uint32_t smem_u32(const void* p) {
    uint32_t a;
    asm("{ .reg .u64 t; cvta.to.shared.u64 t, %1; cvt.u32.u64 %0, t; }"
        : "=r"(a) : "l"(p));
    return a;
}
#define CP_ASYNC16(dst, src) \
    asm volatile("cp.async.cg.shared.global [%0], [%1], 16;" :: "r"(dst), "l"(src))
#define CP_COMMIT() asm volatile("cp.async.commit_group;" ::: "memory")
#define CP_WAIT1()  asm volatile("cp.async.wait_group 1;"  ::: "memory")

// ---------------------------------------------------------------------------
// Weight precompute (8 blocks per matrix)
// ---------------------------------------------------------------------------
__global__ void wsplit_kernel(const float* __restrict__ Wj,
                              const float* __restrict__ Wi,
                              const float* __restrict__ Wf,
                              const float* __restrict__ rWint,
                              const float* __restrict__ rWatm,
                              const float* __restrict__ rWout,
                              const float* __restrict__ Wg,
                              int n_int, int n_atom, int n_out) {
    int m    = blockIdx.x >> 3;
    int part = blockIdx.x & 7;
    int n_mats = 3 + n_int + n_atom + n_out;

    if (m == n_mats) {  // Wg [32 x 128]
        uint32_t* hi = d_wimg + (size_t)m * 16384;
        uint32_t* lo = hi + 2048;
        for (int idx = part * 256 + threadIdx.x; idx < 2048; idx += 2048) {
            int ri = idx & 1;
            int l  = (idx >> 1) & 31;
            int f  = idx >> 6;
            int kt = f & 1, nt = f >> 1;
            int n  = nt * 8 + (l >> 2);
            int k0 = kt * 16 + 2 * (l & 3) + ri * 8;
            uint32_t h, lw;
            build_frag(Wg[k0 * D + n], Wg[(k0 + 1) * D + n], h, lw);
            hi[idx] = h;
            lo[idx] = lw;
        }
        return;
    }

    const float* src;
    if (m == 0)                      src = Wj;
    else if (m == 1)                 src = Wi;
    else if (m == 2)                 src = Wf;
    else if (m < 3 + n_int)          src = rWint + (size_t)(m - 3) * D * D;
    else if (m < 3 + n_int + n_atom) src = rWatm + (size_t)(m - 3 - n_int) * D * D;
    else                             src = rWout + (size_t)(m - 3 - n_int - n_atom) * D * D;

    uint32_t* hi = d_wimg + (size_t)m * 16384;
    uint32_t* lo = hi + 8192;

    for (int idx = part * 1024 + threadIdx.x; idx < (part + 1) * 1024; idx += 256) {
        int ri = idx & 1;
        int l  = (idx >> 1) & 31;
        int f  = idx >> 6;
        int kt = f & 7, nt = f >> 3;
        int n  = nt * 8 + (l >> 2);
        int k0 = kt * 16 + 2 * (l & 3) + ri * 8;
        uint32_t h, lw;
        build_frag(src[k0 * D + n], src[(k0 + 1) * D + n], h, lw);
        hi[idx] = h;
        lo[idx] = lw;
    }
}

// ---------------------------------------------------------------------------
// MMA stage with B in smem: pass-separated, 4-nt register chunks.
// ---------------------------------------------------------------------------
__device__ __forceinline__ void stage_mma_smem(const uint32_t* wsm, int loff,
                                               const uint32_t* ahi, const uint32_t* alo,
                                               float* acc) {
    const char* base = reinterpret_cast<const char*>(wsm);
    #pragma unroll
    for (int kt = 0; kt < 8; kt++) {
        #pragma unroll
        for (int c = 0; c < 4; c++) {
            uint2 bh[4], bl[4];
            #pragma unroll
            for (int i = 0; i < 4; i++)
                bh[i] = *reinterpret_cast<const uint2*>(base + ((c * 4 + i) * 8 + kt) * 256 + loff);
            #pragma unroll
            for (int i = 0; i < 4; i++)
                bl[i] = *reinterpret_cast<const uint2*>(base + 32768 + ((c * 4 + i) * 8 + kt) * 256 + loff);
            #pragma unroll
            for (int i = 0; i < 4; i++)
                mma_bf16(acc + (c * 4 + i) * 4, ahi + kt * 4, bh[i].x, bh[i].y);
            #pragma unroll
            for (int i = 0; i < 4; i++)
                mma_bf16(acc + (c * 4 + i) * 4, alo + kt * 4, bh[i].x, bh[i].y);
            #pragma unroll
            for (int i = 0; i < 4; i++)
                mma_bf16(acc + (c * 4 + i) * 4, ahi + kt * 4, bl[i].x, bl[i].y);
        }
    }
}

// ---------------------------------------------------------------------------
// Head kernel: A = ssp(x); mj = ssp(A@Wj+bj); v = ssp(A@Wi+bi)
// ---------------------------------------------------------------------------
static constexpr int HEAD_SMEM = (16384 + 128) * 4;

__global__ void __launch_bounds__(256, 1)
tc_head_kernel(const float* __restrict__ x,
               const float* __restrict__ bj, const float* __restrict__ bi,
               float* __restrict__ mj, float* __restrict__ v, int N) {
    extern __shared__ uint32_t sm[];
    float* bias_s = reinterpret_cast<float*>(sm + 16384);

    const int t = threadIdx.x, w = t >> 5, l = t & 31;
    const int g = l >> 2, m4 = l & 3;
    const int loff = l * 8;
    const int row_lo = blockIdx.x * 128 + w * 16 + g;
    const int row_hi = row_lo + 8;
    const int cb = 2 * m4;

    uint32_t ahi[32], alo[32];
    #pragma unroll
    for (int nt = 0; nt < 16; nt++) {
        int c0 = nt * 8 + cb;
        float2 a = (row_lo < N) ? *reinterpret_cast<const float2*>(x + (size_t)row_lo * D + c0)
                                : make_float2(0.f, 0.f);
        float2 b = (row_hi < N) ? *reinterpret_cast<const float2*>(x + (size_t)row_hi * D + c0)
                                : make_float2(0.f, 0.f);
        int base = (nt >> 1) * 4 + (nt & 1) * 2;
        build_frag(sspf(a.x), sspf(a.y), ahi[base], alo[base]);
        build_frag(sspf(b.x), sspf(b.y), ahi[base + 1], alo[base + 1]);
    }

    for (int s = 0; s < 2; s++) {
        __syncthreads();
        const uint4* src = reinterpret_cast<const uint4*>(d_wimg + (size_t)s * 16384);
        uint4* dst = reinterpret_cast<uint4*>(sm);
        #pragma unroll
        for (int i = 0; i < 16; i++)
            dst[t + 256 * i] = src[t + 256 * i];
        if (t < 32)
            reinterpret_cast<float4*>(bias_s)[t] =
                reinterpret_cast<const float4*>(s ? bi : bj)[t];
        __syncthreads();

        float acc[64];
        #pragma unroll
        for (int i = 0; i < 64; i++) acc[i] = 0.0f;
        stage_mma_smem(sm, loff, ahi, alo, acc);

        float* outp = s ? v : mj;
        #pragma unroll
        for (int nt = 0; nt < 16; nt++) {
            int c0 = nt * 8 + cb;
            float bv0 = bias_s[c0], bv1 = bias_s[c0 + 1];
            float s0 = sspf(acc[nt * 4 + 0] + bv0);
            float s1 = sspf(acc[nt * 4 + 1] + bv1);
            float s2 = sspf(acc[nt * 4 + 2] + bv0);
            float s3 = sspf(acc[nt * 4 + 3] + bv1);
            if (row_lo < N)
                *reinterpret_cast<float2*>(outp + (size_t)row_lo * D + c0) = make_float2(s0, s1);
            if (row_hi < N)
                *reinterpret_cast<float2*>(outp + (size_t)row_hi * D + c0) = make_float2(s2, s3);
        }
    }
}

// ---------------------------------------------------------------------------
// Tail kernel (R6 proven): register-chained, cp.async double-buffered weights
// ---------------------------------------------------------------------------
static constexpr int BUFW = 16512;
static constexpr int TAIL_SMEM = (2 * BUFW + 128) * 4;

__device__ __forceinline__ void issue_stage_copy(uint32_t buf_addr,
                                                 const uint32_t* img,
                                                 const float* bias, int t) {
    #pragma unroll
    for (int i = 0; i < 16; i++)
        CP_ASYNC16(buf_addr + (t + 256 * i) * 16, img + (t + 256 * i) * 4);
    if (t < 32)
        CP_ASYNC16(buf_addr + 16384 * 4 + t * 16, bias + t * 4);
}

__global__ void __launch_bounds__(256, 1)
tc_tail_kernel(const float* __restrict__ v_in, const float* __restrict__ x,
               const float* __restrict__ u,
               const float* __restrict__ rbint, const float* __restrict__ bf,
               const float* __restrict__ rbatm, const float* __restrict__ rbout,
               int n_int, int n_atom, int n_out,
               float* __restrict__ h_out, float* __restrict__ o_out, int N) {
    extern __shared__ uint32_t sm[];
    float* u_s = reinterpret_cast<float*>(sm + 2 * BUFW);
    const uint32_t sm_addr = smem_u32(sm);

    const int t = threadIdx.x, w = t >> 5, l = t & 31;
    const int g = l >> 2, m4 = l & 3;
    const int loff = l * 8;
    const int row_lo = blockIdx.x * 128 + w * 16 + g;
    const int row_hi = row_lo + 8;
    const int cb = 2 * m4;

    if (t < 32)
        reinterpret_cast<float4*>(u_s)[t] = reinterpret_cast<const float4*>(u)[t];

    const int total = 2 * n_int + 1 + 2 * n_atom + 2 * n_out;

    auto stage_desc = [&](int s, int& mat, const float*& bias, int& mode, bool& storeh) {
        storeh = false;
        if (s < 2 * n_int) {
            mat = 3 + (s >> 1); bias = rbint + (size_t)(s >> 1) * D;
            mode = (s & 1) ? 1 : 0;
        } else if (s == 2 * n_int) {
            mat = 2; bias = bf; mode = 2; storeh = (n_atom == 0);
        } else {
            int s2 = s - 2 * n_int - 1;
            if (s2 < 2 * n_atom) {
                mat = 3 + n_int + (s2 >> 1); bias = rbatm + (size_t)(s2 >> 1) * D;
                mode = (s2 & 1) ? 1 : 0;
                storeh = (s2 == 2 * n_atom - 1);
            } else {
                int s3 = s2 - 2 * n_atom;
                mat = 3 + n_int + n_atom + (s3 >> 1); bias = rbout + (size_t)(s3 >> 1) * D;
                mode = (s3 & 1) ? ((s3 == 2 * n_out - 1) ? 3 : 1) : 0;
            }
        }
    };

    {
        int mat; const float* bias; int mode; bool sh;
        stage_desc(0, mat, bias, mode, sh);
        issue_stage_copy(sm_addr, d_wimg + (size_t)mat * 16384, bias, t);
        CP_COMMIT();
    }

    float vr[64];
    uint32_t ahi[32], alo[32];
    #pragma unroll
    for (int nt = 0; nt < 16; nt++) {
        int c0 = nt * 8 + cb;
        float2 a = (row_lo < N) ? *reinterpret_cast<const float2*>(v_in + (size_t)row_lo * D + c0)
                                : make_float2(0.f, 0.f);
        float2 b = (row_hi < N) ? *reinterpret_cast<const float2*>(v_in + (size_t)row_hi * D + c0)
                                : make_float2(0.f, 0.f);
        vr[nt * 4 + 0] = a.x; vr[nt * 4 + 1] = a.y;
        vr[nt * 4 + 2] = b.x; vr[nt * 4 + 3] = b.y;
        int base = (nt >> 1) * 4 + (nt & 1) * 2;
        build_frag(sspf(a.x), sspf(a.y), ahi[base], alo[base]);
        build_frag(sspf(b.x), sspf(b.y), ahi[base + 1], alo[base + 1]);
    }

    for (int s = 0; s < total; s++) {
        int mat; const float* bias; int mode; bool storeh;
        stage_desc(s, mat, bias, mode, storeh);

        if (s + 1 < total) {
            int nmat; const float* nbias; int nmode; bool nsh;
            stage_desc(s + 1, nmat, nbias, nmode, nsh);
            issue_stage_copy(sm_addr + ((s + 1) & 1) * BUFW * 4,
                             d_wimg + (size_t)nmat * 16384, nbias, t);
        }
        CP_COMMIT();
        CP_WAIT1();
        __syncthreads();

        const uint32_t* wbuf = sm + (s & 1) * BUFW;
        const float* bias_s = reinterpret_cast<const float*>(wbuf + 16384);

        float acc[64];
        #pragma unroll
        for (int i = 0; i < 64; i++) acc[i] = 0.0f;
        stage_mma_smem(wbuf, loff, ahi, alo, acc);

        #pragma unroll
        for (int nt = 0; nt < 16; nt++) {
            int c0 = nt * 8 + cb;
            float bv0 = bias_s[c0], bv1 = bias_s[c0 + 1];
            float v0 = acc[nt * 4 + 0] + bv0;
            float v1 = acc[nt * 4 + 1] + bv1;
            float v2 = acc[nt * 4 + 2] + bv0;
            float v3 = acc[nt * 4 + 3] + bv1;
            if (mode == 1 || mode == 3) {
                v0 += vr[nt * 4 + 0]; v1 += vr[nt * 4 + 1];
                v2 += vr[nt * 4 + 2]; v3 += vr[nt * 4 + 3];
            }
            if (mode == 2) {
                float2 xl = (row_lo < N) ? *reinterpret_cast<const float2*>(x + (size_t)row_lo * D + c0)
                                         : make_float2(0.f, 0.f);
                float2 xh = (row_hi < N) ? *reinterpret_cast<const float2*>(x + (size_t)row_hi * D + c0)
                                         : make_float2(0.f, 0.f);
                float u0 = u_s[c0], u1 = u_s[c0 + 1];
                v0 += u0 * sspf(xl.x); v1 += u1 * sspf(xl.y);
                v2 += u0 * sspf(xh.x); v3 += u1 * sspf(xh.y);
            }
            if (mode == 1 || mode == 2) {
                vr[nt * 4 + 0] = v0; vr[nt * 4 + 1] = v1;
                vr[nt * 4 + 2] = v2; vr[nt * 4 + 3] = v3;
            }
            float s0 = sspf(v0), s1 = sspf(v1), s2 = sspf(v2), s3 = sspf(v3);
            if (mode == 3) {
                if (row_lo < N)
                    *reinterpret_cast<float2*>(o_out + (size_t)row_lo * D + c0) = make_float2(s0, s1);
                if (row_hi < N)
                    *reinterpret_cast<float2*>(o_out + (size_t)row_hi * D + c0) = make_float2(s2, s3);
            } else {
                int base = (nt >> 1) * 4 + (nt & 1) * 2;
                build_frag(s0, s1, ahi[base], alo[base]);
                build_frag(s2, s3, ahi[base + 1], alo[base + 1]);
            }
        }

        if (storeh) {
            #pragma unroll
            for (int nt = 0; nt < 16; nt++) {
                int c0 = nt * 8 + cb;
                if (row_lo < N)
                    *reinterpret_cast<float2*>(h_out + (size_t)row_lo * D + c0) =
                        make_float2(vr[nt * 4 + 0], vr[nt * 4 + 1]);
                if (row_hi < N)
                    *reinterpret_cast<float2*>(h_out + (size_t)row_hi * D + c0) =
                        make_float2(vr[nt * 4 + 2], vr[nt * 4 + 3]);
            }
        }
        __syncthreads();
    }
}

// ---------------------------------------------------------------------------
// Edge kernel v2: HMMA gate + ROW-MAJOR memory phases via smem staging.
// Warp = 16 edges. g staged row-major -> frags from smem; gate staged
// row-major -> per-edge FULL-ROW mj gather (float4) and FULL-ROW red.v4.
// ---------------------------------------------------------------------------
static constexpr int EDGE_SMEM = (4096 + 8 * 16 * 132) * 4;   // 84 KB

__global__ void __launch_bounds__(256)
edge_mma_kernel(const float* __restrict__ g,
                const int* __restrict__ idx_i,
                const int* __restrict__ idx_j,
                const float* __restrict__ mj,
                float* __restrict__ v,
                int E, int wg_slot) {
    extern __shared__ uint32_t esm[];
    uint32_t* wgs = esm;                                  // 4096 words
    float* stag_all = reinterpret_cast<float*>(esm + 4096);

    {
        const uint4* src = reinterpret_cast<const uint4*>(d_wimg + (size_t)wg_slot * 16384);
        uint4* dst = reinterpret_cast<uint4*>(wgs);
        #pragma unroll
        for (int i = threadIdx.x; i < 1024; i += 256)
            dst[i] = src[i];
    }
    __syncthreads();

    const int t = threadIdx.x, l = t & 31, w = t >> 5;
    const int gq = l >> 2, m4 = l & 3;
    const int e0 = (blockIdx.x * 8 + w) * 16;
    if (e0 >= E) return;
    const int nb = min(16, E - e0);

    float* stag = stag_all + w * 16 * 132;

    // edge indices: lane l holds edge e0+l (l < nb)
    int iv = 0, jv = 0;
    if (l < nb) { iv = __ldg(idx_i + e0 + l); jv = __ldg(idx_j + e0 + l); }

    // stage g rows row-major (stride 132 floats): 4 float4 instrs cover 16 rows
    #pragma unroll
    for (int rr = 0; rr < 4; rr++) {
        int r = rr * 4 + (l >> 3);
        if (r < nb) {
            float4 gv = *reinterpret_cast<const float4*>(g + (size_t)(e0 + r) * 32 + (l & 7) * 4);
            *reinterpret_cast<float4*>(stag + r * 132 + (l & 7) * 4) = gv;
        }
    }
    __syncwarp();

    // build A-fragments from staged g (rows gq and 8+gq)
    uint32_t ahi[8], alo[8];
    #pragma unroll
    for (int kt = 0; kt < 2; kt++) {
        int kb = kt * 16 + 2 * m4;
        float2 p00 = (gq < nb)     ? *reinterpret_cast<const float2*>(stag + gq * 132 + kb)
                                   : make_float2(0.f, 0.f);
        float2 p01 = (gq < nb)     ? *reinterpret_cast<const float2*>(stag + gq * 132 + kb + 8)
                                   : make_float2(0.f, 0.f);
        float2 p10 = (8 + gq < nb) ? *reinterpret_cast<const float2*>(stag + (8 + gq) * 132 + kb)
                                   : make_float2(0.f, 0.f);
        float2 p11 = (8 + gq < nb) ? *reinterpret_cast<const float2*>(stag + (8 + gq) * 132 + kb + 8)
                                   : make_float2(0.f, 0.f);
        build_frag(p00.x, p00.y, ahi[kt * 4 + 0], alo[kt * 4 + 0]);
        build_frag(p10.x, p10.y, ahi[kt * 4 + 1], alo[kt * 4 + 1]);
        build_frag(p01.x, p01.y, ahi[kt * 4 + 2], alo[kt * 4 + 2]);
        build_frag(p11.x, p11.y, ahi[kt * 4 + 3], alo[kt * 4 + 3]);
    }
    __syncwarp();   // all lanes done reading g staging

    // gate[16,128] = g @ Wg  (bf16 split, fp32 acc)
    float acc[64];
    #pragma unroll
    for (int i = 0; i < 64; i++) acc[i] = 0.0f;

    const char* base = reinterpret_cast<const char*>(wgs);
    const int loff = l * 8;
    #pragma unroll
    for (int nt = 0; nt < 16; nt++) {
        #pragma unroll
        for (int kt = 0; kt < 2; kt++) {
            uint2 bh = *reinterpret_cast<const uint2*>(base + (nt * 2 + kt) * 256 + loff);
            mma_bf16(acc + nt * 4, ahi + kt * 4, bh.x, bh.y);
            mma_bf16(acc + nt * 4, alo + kt * 4, bh.x, bh.y);
            uint2 bl = *reinterpret_cast<const uint2*>(base + 8192 + (nt * 2 + kt) * 256 + loff);
            mma_bf16(acc + nt * 4, ahi + kt * 4, bl.x, bl.y);
        }
    }

    // stage gate rows row-major (overwrites g staging)
    #pragma unroll
    for (int nt = 0; nt < 16; nt++) {
        int c0 = nt * 8 + 2 * m4;
        if (gq < nb)
            *reinterpret_cast<float2*>(stag + gq * 132 + c0) =
                make_float2(acc[nt * 4 + 0], acc[nt * 4 + 1]);
        if (8 + gq < nb)
            *reinterpret_cast<float2*>(stag + (8 + gq) * 132 + c0) =
                make_float2(acc[nt * 4 + 2], acc[nt * 4 + 3]);
    }
    __syncwarp();

    // per-edge FULL-ROW gather + scatter (all 32 lanes on one row)
    for (int r = 0; r < nb; r++) {
        int j = __shfl_sync(0xffffffffu, jv, r);
        int i = __shfl_sync(0xffffffffu, iv, r);
        float4 gt = *reinterpret_cast<const float4*>(stag + r * 132 + l * 4);
        float4 m  = __ldg(reinterpret_cast<const float4*>(mj + (size_t)j * D + l * 4));
        float x0 = gt.x * m.x, x1 = gt.y * m.y, x2 = gt.z * m.z, x3 = gt.w * m.w;
        asm volatile("red.global.add.v4.f32 [%0], {%1, %2, %3, %4};"
                     :: "l"(v + (size_t)i * D + l * 4),
                        "f"(x0), "f"(x1), "f"(x2), "f"(x3) : "memory");
    }
}

// ---------------------------------------------------------------------------
// Host-side dispatch
// ---------------------------------------------------------------------------
extern "C" void kernel_launch(void* const* d_in, const int* in_sizes, int n_in,
                              void* d_out, int out_size) {
    const float* x     = (const float*)d_in[0];
    const float* g_ij  = (const float*)d_in[1];
    const float* Wf    = (const float*)d_in[2];
    const float* bf    = (const float*)d_in[3];
    const float* Wg    = (const float*)d_in[4];
    const float* Wj    = (const float*)d_in[5];
    const float* bj    = (const float*)d_in[6];
    const float* Wi    = (const float*)d_in[7];
    const float* bi    = (const float*)d_in[8];
    const float* u     = (const float*)d_in[9];
    const float* rWint = (const float*)d_in[10];
    const float* rbint = (const float*)d_in[11];
    const float* rWatm = (const float*)d_in[12];
    const float* rbatm = (const float*)d_in[13];
    const float* rWout = (const float*)d_in[14];
    const float* rbout = (const float*)d_in[15];
    const int*   idx_i = (const int*)d_in[16];
    const int*   idx_j = (const int*)d_in[17];

    const int N      = in_sizes[0] / D;
    const int E      = in_sizes[16];
    const int n_int  = in_sizes[11] / D;
    const int n_atom = in_sizes[13] / D;
    const int n_out  = in_sizes[15] / D;

    if (N > MAXN) return;
    const int n_mats = 3 + n_int + n_atom + n_out;
    if (n_mats + 1 > MAXMATS) return;

    float *mj, *v;
    cudaGetSymbolAddress((void**)&mj, d_mj);
    cudaGetSymbolAddress((void**)&v,  d_v);

    float* o_out = (float*)d_out;                 // o -> first N*D
    float* h_out = (float*)d_out + (size_t)N * D; // h -> second N*D

    cudaFuncSetAttribute(tc_head_kernel, cudaFuncAttributeMaxDynamicSharedMemorySize, HEAD_SMEM);
    cudaFuncSetAttribute(tc_tail_kernel, cudaFuncAttributeMaxDynamicSharedMemorySize, TAIL_SMEM);
    cudaFuncSetAttribute(edge_mma_kernel, cudaFuncAttributeMaxDynamicSharedMemorySize, EDGE_SMEM);

    const int tiles = (N + 127) / 128;

    // 0) split + permute weights (incl. Wg at slot n_mats)
    wsplit_kernel<<<(n_mats + 1) * 8, 256>>>(Wj, Wi, Wf, rWint, rWatm, rWout, Wg,
                                             n_int, n_atom, n_out);

    // 1) mj = ssp(ssp(x)@Wj+bj); v = ssp(ssp(x)@Wi+bi)
    tc_head_kernel<<<tiles, 256, HEAD_SMEM>>>(x, bj, bi, mj, v, N);

    // 2) v += segment_sum( (g_ij @ Wg) * mj[idx_j], idx_i )  [row-major phases]
    {
        int batches = (E + 15) / 16;
        int blocks  = (batches + 7) / 8;
        edge_mma_kernel<<<blocks, 256, EDGE_SMEM>>>(g_ij, idx_i, idx_j, mj, v, E, n_mats);
    }

    // 3) fused register-chained tail (R6 design)
    tc_tail_kernel<<<tiles, 256, TAIL_SMEM>>>(
        v, x, u, rbint, bf, rbatm, rbout, n_int, n_atom, n_out, h_out, o_out, N);
}

// round 14
// speedup vs baseline: 1.1497x; 1.0671x over previous
#include <cuda_runtime.h>
#include <cuda_bf16.h>
#include <math.h>
#include <stdint.h>

#define D 128
static constexpr int MAXN = 51200;
static constexpr int MAXMATS = 16;   // slots; last used slot holds Wg frags

// ---------------------------------------------------------------------------
// Scratch (no allocs allowed -> device globals)
// ---------------------------------------------------------------------------
__device__ float d_mj[MAXN * D];
__device__ float d_v [MAXN * D];
__device__ __align__(16) uint32_t d_wimg[MAXMATS * 16384];

__device__ __forceinline__ float sspf(float x) {
    return fmaxf(x, 0.0f) + __logf(1.0f + __expf(-fabsf(x))) - 0.69314718055994530942f;
}

// ---------------------------------------------------------------------------
// HMMA m16n8k16 bf16 (base PTX) + frag building
// ---------------------------------------------------------------------------
__device__ __forceinline__ void mma_bf16(float* d, const uint32_t* a,
                                         uint32_t b0, uint32_t b1) {
    asm volatile(
        "mma.sync.aligned.m16n8k16.row.col.f32.bf16.bf16.f32 "
        "{%0,%1,%2,%3}, {%4,%5,%6,%7}, {%8,%9}, {%0,%1,%2,%3};"
        : "+f"(d[0]), "+f"(d[1]), "+f"(d[2]), "+f"(d[3])
        : "r"(a[0]), "r"(a[1]), "r"(a[2]), "r"(a[3]), "r"(b0), "r"(b1));
}

__device__ __forceinline__ void build_frag(float s0, float s1,
                                           uint32_t& hi, uint32_t& lo) {
    __nv_bfloat162 h2 = __floats2bfloat162_rn(s0, s1);
    float l0 = s0 - __bfloat162float(h2.x);
    float l1 = s1 - __bfloat162float(h2.y);
    __nv_bfloat162 l2 = __floats2bfloat162_rn(l0, l1);
    hi = *reinterpret_cast<uint32_t*>(&h2);
    lo = *reinterpret_cast<uint32_t*>(&l2);
}

// ---------------------------------------------------------------------------
// cp.async helpers
// ---------------------------------------------------------------------------
__device__ __forceinline__ uint32_t smem_u32(const void* p) {
    uint32_t a;
    asm("{ .reg .u64 t; cvta.to.shared.u64 t, %1; cvt.u32.u64 %0, t; }"
        : "=r"(a) : "l"(p));
    return a;
}
#define CP_ASYNC16(dst, src) \
    asm volatile("cp.async.cg.shared.global [%0], [%1], 16;" :: "r"(dst), "l"(src))
#define CP_COMMIT() asm volatile("cp.async.commit_group;" ::: "memory")
#define CP_WAIT1()  asm volatile("cp.async.wait_group 1;"  ::: "memory")

// ---------------------------------------------------------------------------
// Weight precompute (8 blocks per matrix)
// ---------------------------------------------------------------------------
__global__ void wsplit_kernel(const float* __restrict__ Wj,
                              const float* __restrict__ Wi,
                              const float* __restrict__ Wf,
                              const float* __restrict__ rWint,
                              const float* __restrict__ rWatm,
                              const float* __restrict__ rWout,
                              const float* __restrict__ Wg,
                              int n_int, int n_atom, int n_out) {
    int m    = blockIdx.x >> 3;
    int part = blockIdx.x & 7;
    int n_mats = 3 + n_int + n_atom + n_out;

    if (m == n_mats) {  // Wg [32 x 128]
        uint32_t* hi = d_wimg + (size_t)m * 16384;
        uint32_t* lo = hi + 2048;
        for (int idx = part * 256 + threadIdx.x; idx < 2048; idx += 2048) {
            int ri = idx & 1;
            int l  = (idx >> 1) & 31;
            int f  = idx >> 6;
            int kt = f & 1, nt = f >> 1;
            int n  = nt * 8 + (l >> 2);
            int k0 = kt * 16 + 2 * (l & 3) + ri * 8;
            uint32_t h, lw;
            build_frag(Wg[k0 * D + n], Wg[(k0 + 1) * D + n], h, lw);
            hi[idx] = h;
            lo[idx] = lw;
        }
        return;
    }

    const float* src;
    if (m == 0)                      src = Wj;
    else if (m == 1)                 src = Wi;
    else if (m == 2)                 src = Wf;
    else if (m < 3 + n_int)          src = rWint + (size_t)(m - 3) * D * D;
    else if (m < 3 + n_int + n_atom) src = rWatm + (size_t)(m - 3 - n_int) * D * D;
    else                             src = rWout + (size_t)(m - 3 - n_int - n_atom) * D * D;

    uint32_t* hi = d_wimg + (size_t)m * 16384;
    uint32_t* lo = hi + 8192;

    for (int idx = part * 1024 + threadIdx.x; idx < (part + 1) * 1024; idx += 256) {
        int ri = idx & 1;
        int l  = (idx >> 1) & 31;
        int f  = idx >> 6;
        int kt = f & 7, nt = f >> 3;
        int n  = nt * 8 + (l >> 2);
        int k0 = kt * 16 + 2 * (l & 3) + ri * 8;
        uint32_t h, lw;
        build_frag(src[k0 * D + n], src[(k0 + 1) * D + n], h, lw);
        hi[idx] = h;
        lo[idx] = lw;
    }
}

// ---------------------------------------------------------------------------
// MMA stage with B in smem: pass-separated, 4-nt register chunks.
// ---------------------------------------------------------------------------
__device__ __forceinline__ void stage_mma_smem(const uint32_t* wsm, int loff,
                                               const uint32_t* ahi, const uint32_t* alo,
                                               float* acc) {
    const char* base = reinterpret_cast<const char*>(wsm);
    #pragma unroll
    for (int kt = 0; kt < 8; kt++) {
        #pragma unroll
        for (int c = 0; c < 4; c++) {
            uint2 bh[4], bl[4];
            #pragma unroll
            for (int i = 0; i < 4; i++)
                bh[i] = *reinterpret_cast<const uint2*>(base + ((c * 4 + i) * 8 + kt) * 256 + loff);
            #pragma unroll
            for (int i = 0; i < 4; i++)
                bl[i] = *reinterpret_cast<const uint2*>(base + 32768 + ((c * 4 + i) * 8 + kt) * 256 + loff);
            #pragma unroll
            for (int i = 0; i < 4; i++)
                mma_bf16(acc + (c * 4 + i) * 4, ahi + kt * 4, bh[i].x, bh[i].y);
            #pragma unroll
            for (int i = 0; i < 4; i++)
                mma_bf16(acc + (c * 4 + i) * 4, alo + kt * 4, bh[i].x, bh[i].y);
            #pragma unroll
            for (int i = 0; i < 4; i++)
                mma_bf16(acc + (c * 4 + i) * 4, ahi + kt * 4, bl[i].x, bl[i].y);
        }
    }
}

// ---------------------------------------------------------------------------
// Head kernel: A = ssp(x); mj = ssp(A@Wj+bj); v = ssp(A@Wi+bi)
// ---------------------------------------------------------------------------
static constexpr int HEAD_SMEM = (16384 + 128) * 4;

__global__ void __launch_bounds__(256, 1)
tc_head_kernel(const float* __restrict__ x,
               const float* __restrict__ bj, const float* __restrict__ bi,
               float* __restrict__ mj, float* __restrict__ v, int N) {
    extern __shared__ uint32_t sm[];
    float* bias_s = reinterpret_cast<float*>(sm + 16384);

    const int t = threadIdx.x, w = t >> 5, l = t & 31;
    const int g = l >> 2, m4 = l & 3;
    const int loff = l * 8;
    const int row_lo = blockIdx.x * 128 + w * 16 + g;
    const int row_hi = row_lo + 8;
    const int cb = 2 * m4;

    uint32_t ahi[32], alo[32];
    #pragma unroll
    for (int nt = 0; nt < 16; nt++) {
        int c0 = nt * 8 + cb;
        float2 a = (row_lo < N) ? *reinterpret_cast<const float2*>(x + (size_t)row_lo * D + c0)
                                : make_float2(0.f, 0.f);
        float2 b = (row_hi < N) ? *reinterpret_cast<const float2*>(x + (size_t)row_hi * D + c0)
                                : make_float2(0.f, 0.f);
        int base = (nt >> 1) * 4 + (nt & 1) * 2;
        build_frag(sspf(a.x), sspf(a.y), ahi[base], alo[base]);
        build_frag(sspf(b.x), sspf(b.y), ahi[base + 1], alo[base + 1]);
    }

    for (int s = 0; s < 2; s++) {
        __syncthreads();
        const uint4* src = reinterpret_cast<const uint4*>(d_wimg + (size_t)s * 16384);
        uint4* dst = reinterpret_cast<uint4*>(sm);
        #pragma unroll
        for (int i = 0; i < 16; i++)
            dst[t + 256 * i] = src[t + 256 * i];
        if (t < 32)
            reinterpret_cast<float4*>(bias_s)[t] =
                reinterpret_cast<const float4*>(s ? bi : bj)[t];
        __syncthreads();

        float acc[64];
        #pragma unroll
        for (int i = 0; i < 64; i++) acc[i] = 0.0f;
        stage_mma_smem(sm, loff, ahi, alo, acc);

        float* outp = s ? v : mj;
        #pragma unroll
        for (int nt = 0; nt < 16; nt++) {
            int c0 = nt * 8 + cb;
            float bv0 = bias_s[c0], bv1 = bias_s[c0 + 1];
            float s0 = sspf(acc[nt * 4 + 0] + bv0);
            float s1 = sspf(acc[nt * 4 + 1] + bv1);
            float s2 = sspf(acc[nt * 4 + 2] + bv0);
            float s3 = sspf(acc[nt * 4 + 3] + bv1);
            if (row_lo < N)
                *reinterpret_cast<float2*>(outp + (size_t)row_lo * D + c0) = make_float2(s0, s1);
            if (row_hi < N)
                *reinterpret_cast<float2*>(outp + (size_t)row_hi * D + c0) = make_float2(s2, s3);
        }
    }
}

// ---------------------------------------------------------------------------
// Tail kernel (R6 proven): register-chained, cp.async double-buffered weights
// ---------------------------------------------------------------------------
static constexpr int BUFW = 16512;
static constexpr int TAIL_SMEM = (2 * BUFW + 128) * 4;

__device__ __forceinline__ void issue_stage_copy(uint32_t buf_addr,
                                                 const uint32_t* img,
                                                 const float* bias, int t) {
    #pragma unroll
    for (int i = 0; i < 16; i++)
        CP_ASYNC16(buf_addr + (t + 256 * i) * 16, img + (t + 256 * i) * 4);
    if (t < 32)
        CP_ASYNC16(buf_addr + 16384 * 4 + t * 16, bias + t * 4);
}

__global__ void __launch_bounds__(256, 1)
tc_tail_kernel(const float* __restrict__ v_in, const float* __restrict__ x,
               const float* __restrict__ u,
               const float* __restrict__ rbint, const float* __restrict__ bf,
               const float* __restrict__ rbatm, const float* __restrict__ rbout,
               int n_int, int n_atom, int n_out,
               float* __restrict__ h_out, float* __restrict__ o_out, int N) {
    extern __shared__ uint32_t sm[];
    float* u_s = reinterpret_cast<float*>(sm + 2 * BUFW);
    const uint32_t sm_addr = smem_u32(sm);

    const int t = threadIdx.x, w = t >> 5, l = t & 31;
    const int g = l >> 2, m4 = l & 3;
    const int loff = l * 8;
    const int row_lo = blockIdx.x * 128 + w * 16 + g;
    const int row_hi = row_lo + 8;
    const int cb = 2 * m4;

    if (t < 32)
        reinterpret_cast<float4*>(u_s)[t] = reinterpret_cast<const float4*>(u)[t];

    const int total = 2 * n_int + 1 + 2 * n_atom + 2 * n_out;

    auto stage_desc = [&](int s, int& mat, const float*& bias, int& mode, bool& storeh) {
        storeh = false;
        if (s < 2 * n_int) {
            mat = 3 + (s >> 1); bias = rbint + (size_t)(s >> 1) * D;
            mode = (s & 1) ? 1 : 0;
        } else if (s == 2 * n_int) {
            mat = 2; bias = bf; mode = 2; storeh = (n_atom == 0);
        } else {
            int s2 = s - 2 * n_int - 1;
            if (s2 < 2 * n_atom) {
                mat = 3 + n_int + (s2 >> 1); bias = rbatm + (size_t)(s2 >> 1) * D;
                mode = (s2 & 1) ? 1 : 0;
                storeh = (s2 == 2 * n_atom - 1);
            } else {
                int s3 = s2 - 2 * n_atom;
                mat = 3 + n_int + n_atom + (s3 >> 1); bias = rbout + (size_t)(s3 >> 1) * D;
                mode = (s3 & 1) ? ((s3 == 2 * n_out - 1) ? 3 : 1) : 0;
            }
        }
    };

    {
        int mat; const float* bias; int mode; bool sh;
        stage_desc(0, mat, bias, mode, sh);
        issue_stage_copy(sm_addr, d_wimg + (size_t)mat * 16384, bias, t);
        CP_COMMIT();
    }

    float vr[64];
    uint32_t ahi[32], alo[32];
    #pragma unroll
    for (int nt = 0; nt < 16; nt++) {
        int c0 = nt * 8 + cb;
        float2 a = (row_lo < N) ? *reinterpret_cast<const float2*>(v_in + (size_t)row_lo * D + c0)
                                : make_float2(0.f, 0.f);
        float2 b = (row_hi < N) ? *reinterpret_cast<const float2*>(v_in + (size_t)row_hi * D + c0)
                                : make_float2(0.f, 0.f);
        vr[nt * 4 + 0] = a.x; vr[nt * 4 + 1] = a.y;
        vr[nt * 4 + 2] = b.x; vr[nt * 4 + 3] = b.y;
        int base = (nt >> 1) * 4 + (nt & 1) * 2;
        build_frag(sspf(a.x), sspf(a.y), ahi[base], alo[base]);
        build_frag(sspf(b.x), sspf(b.y), ahi[base + 1], alo[base + 1]);
    }

    for (int s = 0; s < total; s++) {
        int mat; const float* bias; int mode; bool storeh;
        stage_desc(s, mat, bias, mode, storeh);

        if (s + 1 < total) {
            int nmat; const float* nbias; int nmode; bool nsh;
            stage_desc(s + 1, nmat, nbias, nmode, nsh);
            issue_stage_copy(sm_addr + ((s + 1) & 1) * BUFW * 4,
                             d_wimg + (size_t)nmat * 16384, nbias, t);
        }
        CP_COMMIT();
        CP_WAIT1();
        __syncthreads();

        const uint32_t* wbuf = sm + (s & 1) * BUFW;
        const float* bias_s = reinterpret_cast<const float*>(wbuf + 16384);

        float acc[64];
        #pragma unroll
        for (int i = 0; i < 64; i++) acc[i] = 0.0f;
        stage_mma_smem(wbuf, loff, ahi, alo, acc);

        #pragma unroll
        for (int nt = 0; nt < 16; nt++) {
            int c0 = nt * 8 + cb;
            float bv0 = bias_s[c0], bv1 = bias_s[c0 + 1];
            float v0 = acc[nt * 4 + 0] + bv0;
            float v1 = acc[nt * 4 + 1] + bv1;
            float v2 = acc[nt * 4 + 2] + bv0;
            float v3 = acc[nt * 4 + 3] + bv1;
            if (mode == 1 || mode == 3) {
                v0 += vr[nt * 4 + 0]; v1 += vr[nt * 4 + 1];
                v2 += vr[nt * 4 + 2]; v3 += vr[nt * 4 + 3];
            }
            if (mode == 2) {
                float2 xl = (row_lo < N) ? *reinterpret_cast<const float2*>(x + (size_t)row_lo * D + c0)
                                         : make_float2(0.f, 0.f);
                float2 xh = (row_hi < N) ? *reinterpret_cast<const float2*>(x + (size_t)row_hi * D + c0)
                                         : make_float2(0.f, 0.f);
                float u0 = u_s[c0], u1 = u_s[c0 + 1];
                v0 += u0 * sspf(xl.x); v1 += u1 * sspf(xl.y);
                v2 += u0 * sspf(xh.x); v3 += u1 * sspf(xh.y);
            }
            if (mode == 1 || mode == 2) {
                vr[nt * 4 + 0] = v0; vr[nt * 4 + 1] = v1;
                vr[nt * 4 + 2] = v2; vr[nt * 4 + 3] = v3;
            }
            float s0 = sspf(v0), s1 = sspf(v1), s2 = sspf(v2), s3 = sspf(v3);
            if (mode == 3) {
                if (row_lo < N)
                    *reinterpret_cast<float2*>(o_out + (size_t)row_lo * D + c0) = make_float2(s0, s1);
                if (row_hi < N)
                    *reinterpret_cast<float2*>(o_out + (size_t)row_hi * D + c0) = make_float2(s2, s3);
            } else {
                int base = (nt >> 1) * 4 + (nt & 1) * 2;
                build_frag(s0, s1, ahi[base], alo[base]);
                build_frag(s2, s3, ahi[base + 1], alo[base + 1]);
            }
        }

        if (storeh) {
            #pragma unroll
            for (int nt = 0; nt < 16; nt++) {
                int c0 = nt * 8 + cb;
                if (row_lo < N)
                    *reinterpret_cast<float2*>(h_out + (size_t)row_lo * D + c0) =
                        make_float2(vr[nt * 4 + 0], vr[nt * 4 + 1]);
                if (row_hi < N)
                    *reinterpret_cast<float2*>(h_out + (size_t)row_hi * D + c0) =
                        make_float2(vr[nt * 4 + 2], vr[nt * 4 + 3]);
            }
        }
        __syncthreads();
    }
}

// ---------------------------------------------------------------------------
// Edge kernel: HMMA gate + row-major phases; scatter loop UNROLLED for full
// batches so ptxas front-batches the 16 independent mj LDG.128s (MLP 16).
// ---------------------------------------------------------------------------
static constexpr int EDGE_SMEM = (4096 + 8 * 16 * 132) * 4;   // 84 KB

__device__ __forceinline__ void edge_scatter_one(const float* __restrict__ stag,
                                                 const float* __restrict__ mj,
                                                 float* __restrict__ v,
                                                 int r, int iv, int jv, int l) {
    int j = __shfl_sync(0xffffffffu, jv, r);
    int i = __shfl_sync(0xffffffffu, iv, r);
    float4 gt = *reinterpret_cast<const float4*>(stag + r * 132 + l * 4);
    float4 m  = __ldg(reinterpret_cast<const float4*>(mj + (size_t)j * D + l * 4));
    float x0 = gt.x * m.x, x1 = gt.y * m.y, x2 = gt.z * m.z, x3 = gt.w * m.w;
    asm volatile("red.global.add.v4.f32 [%0], {%1, %2, %3, %4};"
                 :: "l"(v + (size_t)i * D + l * 4),
                    "f"(x0), "f"(x1), "f"(x2), "f"(x3) : "memory");
}

__global__ void __launch_bounds__(256)
edge_mma_kernel(const float* __restrict__ g,
                const int* __restrict__ idx_i,
                const int* __restrict__ idx_j,
                const float* __restrict__ mj,
                float* __restrict__ v,
                int E, int wg_slot) {
    extern __shared__ uint32_t esm[];
    uint32_t* wgs = esm;                                  // 4096 words
    float* stag_all = reinterpret_cast<float*>(esm + 4096);

    {
        const uint4* src = reinterpret_cast<const uint4*>(d_wimg + (size_t)wg_slot * 16384);
        uint4* dst = reinterpret_cast<uint4*>(wgs);
        #pragma unroll
        for (int i = threadIdx.x; i < 1024; i += 256)
            dst[i] = src[i];
    }
    __syncthreads();

    const int t = threadIdx.x, l = t & 31, w = t >> 5;
    const int gq = l >> 2, m4 = l & 3;
    const int e0 = (blockIdx.x * 8 + w) * 16;
    if (e0 >= E) return;
    const int nb = min(16, E - e0);

    float* stag = stag_all + w * 16 * 132;

    // edge indices: lane l holds edge e0+l (l < nb)
    int iv = 0, jv = 0;
    if (l < nb) { iv = __ldg(idx_i + e0 + l); jv = __ldg(idx_j + e0 + l); }

    // stage g rows row-major (stride 132 floats): 4 float4 instrs cover 16 rows
    #pragma unroll
    for (int rr = 0; rr < 4; rr++) {
        int r = rr * 4 + (l >> 3);
        if (r < nb) {
            float4 gv = *reinterpret_cast<const float4*>(g + (size_t)(e0 + r) * 32 + (l & 7) * 4);
            *reinterpret_cast<float4*>(stag + r * 132 + (l & 7) * 4) = gv;
        }
    }
    __syncwarp();

    // build A-fragments from staged g (rows gq and 8+gq)
    uint32_t ahi[8], alo[8];
    #pragma unroll
    for (int kt = 0; kt < 2; kt++) {
        int kb = kt * 16 + 2 * m4;
        float2 p00 = (gq < nb)     ? *reinterpret_cast<const float2*>(stag + gq * 132 + kb)
                                   : make_float2(0.f, 0.f);
        float2 p01 = (gq < nb)     ? *reinterpret_cast<const float2*>(stag + gq * 132 + kb + 8)
                                   : make_float2(0.f, 0.f);
        float2 p10 = (8 + gq < nb) ? *reinterpret_cast<const float2*>(stag + (8 + gq) * 132 + kb)
                                   : make_float2(0.f, 0.f);
        float2 p11 = (8 + gq < nb) ? *reinterpret_cast<const float2*>(stag + (8 + gq) * 132 + kb + 8)
                                   : make_float2(0.f, 0.f);
        build_frag(p00.x, p00.y, ahi[kt * 4 + 0], alo[kt * 4 + 0]);
        build_frag(p10.x, p10.y, ahi[kt * 4 + 1], alo[kt * 4 + 1]);
        build_frag(p01.x, p01.y, ahi[kt * 4 + 2], alo[kt * 4 + 2]);
        build_frag(p11.x, p11.y, ahi[kt * 4 + 3], alo[kt * 4 + 3]);
    }
    __syncwarp();   // all lanes done reading g staging

    // gate[16,128] = g @ Wg  (bf16 split, fp32 acc)
    float acc[64];
    #pragma unroll
    for (int i = 0; i < 64; i++) acc[i] = 0.0f;

    const char* base = reinterpret_cast<const char*>(wgs);
    const int loff = l * 8;
    #pragma unroll
    for (int nt = 0; nt < 16; nt++) {
        #pragma unroll
        for (int kt = 0; kt < 2; kt++) {
            uint2 bh = *reinterpret_cast<const uint2*>(base + (nt * 2 + kt) * 256 + loff);
            mma_bf16(acc + nt * 4, ahi + kt * 4, bh.x, bh.y);
            mma_bf16(acc + nt * 4, alo + kt * 4, bh.x, bh.y);
            uint2 bl = *reinterpret_cast<const uint2*>(base + 8192 + (nt * 2 + kt) * 256 + loff);
            mma_bf16(acc + nt * 4, ahi + kt * 4, bl.x, bl.y);
        }
    }

    // stage gate rows row-major (overwrites g staging)
    #pragma unroll
    for (int nt = 0; nt < 16; nt++) {
        int c0 = nt * 8 + 2 * m4;
        if (gq < nb)
            *reinterpret_cast<float2*>(stag + gq * 132 + c0) =
                make_float2(acc[nt * 4 + 0], acc[nt * 4 + 1]);
        if (8 + gq < nb)
            *reinterpret_cast<float2*>(stag + (8 + gq) * 132 + c0) =
                make_float2(acc[nt * 4 + 2], acc[nt * 4 + 3]);
    }
    __syncwarp();

    // per-edge FULL-ROW gather + scatter; unrolled fast path lets ptxas
    // front-batch all 16 independent mj LDG.128s (MLP=16)
    if (nb == 16) {
        #pragma unroll
        for (int r = 0; r < 16; r++)
            edge_scatter_one(stag, mj, v, r, iv, jv, l);
    } else {
        for (int r = 0; r < nb; r++)
            edge_scatter_one(stag, mj, v, r, iv, jv, l);
    }
}

// ---------------------------------------------------------------------------
// Host-side dispatch
// ---------------------------------------------------------------------------
extern "C" void kernel_launch(void* const* d_in, const int* in_sizes, int n_in,
                              void* d_out, int out_size) {
    const float* x     = (const float*)d_in[0];
    const float* g_ij  = (const float*)d_in[1];
    const float* Wf    = (const float*)d_in[2];
    const float* bf    = (const float*)d_in[3];
    const float* Wg    = (const float*)d_in[4];
    const float* Wj    = (const float*)d_in[5];
    const float* bj    = (const float*)d_in[6];
    const float* Wi    = (const float*)d_in[7];
    const float* bi    = (const float*)d_in[8];
    const float* u     = (const float*)d_in[9];
    const float* rWint = (const float*)d_in[10];
    const float* rbint = (const float*)d_in[11];
    const float* rWatm = (const float*)d_in[12];
    const float* rbatm = (const float*)d_in[13];
    const float* rWout = (const float*)d_in[14];
    const float* rbout = (const float*)d_in[15];
    const int*   idx_i = (const int*)d_in[16];
    const int*   idx_j = (const int*)d_in[17];

    const int N      = in_sizes[0] / D;
    const int E      = in_sizes[16];
    const int n_int  = in_sizes[11] / D;
    const int n_atom = in_sizes[13] / D;
    const int n_out  = in_sizes[15] / D;

    if (N > MAXN) return;
    const int n_mats = 3 + n_int + n_atom + n_out;
    if (n_mats + 1 > MAXMATS) return;

    float *mj, *v;
    cudaGetSymbolAddress((void**)&mj, d_mj);
    cudaGetSymbolAddress((void**)&v,  d_v);

    float* o_out = (float*)d_out;                 // o -> first N*D
    float* h_out = (float*)d_out + (size_t)N * D; // h -> second N*D

    cudaFuncSetAttribute(tc_head_kernel, cudaFuncAttributeMaxDynamicSharedMemorySize, HEAD_SMEM);
    cudaFuncSetAttribute(tc_tail_kernel, cudaFuncAttributeMaxDynamicSharedMemorySize, TAIL_SMEM);
    cudaFuncSetAttribute(edge_mma_kernel, cudaFuncAttributeMaxDynamicSharedMemorySize, EDGE_SMEM);

    const int tiles = (N + 127) / 128;

    // 0) split + permute weights (incl. Wg at slot n_mats)
    wsplit_kernel<<<(n_mats + 1) * 8, 256>>>(Wj, Wi, Wf, rWint, rWatm, rWout, Wg,
                                             n_int, n_atom, n_out);

    // 1) mj = ssp(ssp(x)@Wj+bj); v = ssp(ssp(x)@Wi+bi)
    tc_head_kernel<<<tiles, 256, HEAD_SMEM>>>(x, bj, bi, mj, v, N);

    // 2) v += segment_sum( (g_ij @ Wg) * mj[idx_j], idx_i )
    {
        int batches = (E + 15) / 16;
        int blocks  = (batches + 7) / 8;
        edge_mma_kernel<<<blocks, 256, EDGE_SMEM>>>(g_ij, idx_i, idx_j, mj, v, E, n_mats);
    }

    // 3) fused register-chained tail (R6 design)
    tc_tail_kernel<<<tiles, 256, TAIL_SMEM>>>(
        v, x, u, rbint, bf, rbatm, rbout, n_int, n_atom, n_out, h_out, o_out, N);
}

// round 15
// speedup vs baseline: 1.1914x; 1.0362x over previous
#include <cuda_runtime.h>
#include <cuda_bf16.h>
#include <math.h>
#include <stdint.h>

#define D 128
static constexpr int MAXN = 51200;
static constexpr int MAXMATS = 16;   // slots; last used slot holds Wg frags

// ---------------------------------------------------------------------------
// Scratch (no allocs allowed -> device globals)
// ---------------------------------------------------------------------------
__device__ float d_mj[MAXN * D];
__device__ float d_v [MAXN * D];
__device__ __align__(16) uint32_t d_wimg[MAXMATS * 16384];

__device__ __forceinline__ float sspf(float x) {
    return fmaxf(x, 0.0f) + __logf(1.0f + __expf(-fabsf(x))) - 0.69314718055994530942f;
}

// ---------------------------------------------------------------------------
// HMMA m16n8k16 bf16 (base PTX) + frag building
// ---------------------------------------------------------------------------
__device__ __forceinline__ void mma_bf16(float* d, const uint32_t* a,
                                         uint32_t b0, uint32_t b1) {
    asm volatile(
        "mma.sync.aligned.m16n8k16.row.col.f32.bf16.bf16.f32 "
        "{%0,%1,%2,%3}, {%4,%5,%6,%7}, {%8,%9}, {%0,%1,%2,%3};"
        : "+f"(d[0]), "+f"(d[1]), "+f"(d[2]), "+f"(d[3])
        : "r"(a[0]), "r"(a[1]), "r"(a[2]), "r"(a[3]), "r"(b0), "r"(b1));
}

__device__ __forceinline__ void build_frag(float s0, float s1,
                                           uint32_t& hi, uint32_t& lo) {
    __nv_bfloat162 h2 = __floats2bfloat162_rn(s0, s1);
    float l0 = s0 - __bfloat162float(h2.x);
    float l1 = s1 - __bfloat162float(h2.y);
    __nv_bfloat162 l2 = __floats2bfloat162_rn(l0, l1);
    hi = *reinterpret_cast<uint32_t*>(&h2);
    lo = *reinterpret_cast<uint32_t*>(&l2);
}

// ---------------------------------------------------------------------------
// cp.async helpers
// ---------------------------------------------------------------------------
__device__ __forceinline__ uint32_t smem_u32(const void* p) {
    uint32_t a;
    asm("{ .reg .u64 t; cvta.to.shared.u64 t, %1; cvt.u32.u64 %0, t; }"
        : "=r"(a) : "l"(p));
    return a;
}
#define CP_ASYNC16(dst, src) \
    asm volatile("cp.async.cg.shared.global [%0], [%1], 16;" :: "r"(dst), "l"(src))
#define CP_COMMIT() asm volatile("cp.async.commit_group;" ::: "memory")
#define CP_WAIT1()  asm volatile("cp.async.wait_group 1;"  ::: "memory")
#define CP_WAIT0()  asm volatile("cp.async.wait_group 0;"  ::: "memory")

// ---------------------------------------------------------------------------
// Weight precompute (8 blocks per matrix)
// ---------------------------------------------------------------------------
__global__ void wsplit_kernel(const float* __restrict__ Wj,
                              const float* __restrict__ Wi,
                              const float* __restrict__ Wf,
                              const float* __restrict__ rWint,
                              const float* __restrict__ rWatm,
                              const float* __restrict__ rWout,
                              const float* __restrict__ Wg,
                              int n_int, int n_atom, int n_out) {
    int m    = blockIdx.x >> 3;
    int part = blockIdx.x & 7;
    int n_mats = 3 + n_int + n_atom + n_out;

    if (m == n_mats) {  // Wg [32 x 128]
        uint32_t* hi = d_wimg + (size_t)m * 16384;
        uint32_t* lo = hi + 2048;
        for (int idx = part * 256 + threadIdx.x; idx < 2048; idx += 2048) {
            int ri = idx & 1;
            int l  = (idx >> 1) & 31;
            int f  = idx >> 6;
            int kt = f & 1, nt = f >> 1;
            int n  = nt * 8 + (l >> 2);
            int k0 = kt * 16 + 2 * (l & 3) + ri * 8;
            uint32_t h, lw;
            build_frag(Wg[k0 * D + n], Wg[(k0 + 1) * D + n], h, lw);
            hi[idx] = h;
            lo[idx] = lw;
        }
        return;
    }

    const float* src;
    if (m == 0)                      src = Wj;
    else if (m == 1)                 src = Wi;
    else if (m == 2)                 src = Wf;
    else if (m < 3 + n_int)          src = rWint + (size_t)(m - 3) * D * D;
    else if (m < 3 + n_int + n_atom) src = rWatm + (size_t)(m - 3 - n_int) * D * D;
    else                             src = rWout + (size_t)(m - 3 - n_int - n_atom) * D * D;

    uint32_t* hi = d_wimg + (size_t)m * 16384;
    uint32_t* lo = hi + 8192;

    for (int idx = part * 1024 + threadIdx.x; idx < (part + 1) * 1024; idx += 256) {
        int ri = idx & 1;
        int l  = (idx >> 1) & 31;
        int f  = idx >> 6;
        int kt = f & 7, nt = f >> 3;
        int n  = nt * 8 + (l >> 2);
        int k0 = kt * 16 + 2 * (l & 3) + ri * 8;
        uint32_t h, lw;
        build_frag(src[k0 * D + n], src[(k0 + 1) * D + n], h, lw);
        hi[idx] = h;
        lo[idx] = lw;
    }
}

// ---------------------------------------------------------------------------
// MMA stage with B in smem: pass-separated, 4-nt register chunks.
// ---------------------------------------------------------------------------
__device__ __forceinline__ void stage_mma_smem(const uint32_t* wsm, int loff,
                                               const uint32_t* ahi, const uint32_t* alo,
                                               float* acc) {
    const char* base = reinterpret_cast<const char*>(wsm);
    #pragma unroll
    for (int kt = 0; kt < 8; kt++) {
        #pragma unroll
        for (int c = 0; c < 4; c++) {
            uint2 bh[4], bl[4];
            #pragma unroll
            for (int i = 0; i < 4; i++)
                bh[i] = *reinterpret_cast<const uint2*>(base + ((c * 4 + i) * 8 + kt) * 256 + loff);
            #pragma unroll
            for (int i = 0; i < 4; i++)
                bl[i] = *reinterpret_cast<const uint2*>(base + 32768 + ((c * 4 + i) * 8 + kt) * 256 + loff);
            #pragma unroll
            for (int i = 0; i < 4; i++)
                mma_bf16(acc + (c * 4 + i) * 4, ahi + kt * 4, bh[i].x, bh[i].y);
            #pragma unroll
            for (int i = 0; i < 4; i++)
                mma_bf16(acc + (c * 4 + i) * 4, alo + kt * 4, bh[i].x, bh[i].y);
            #pragma unroll
            for (int i = 0; i < 4; i++)
                mma_bf16(acc + (c * 4 + i) * 4, ahi + kt * 4, bl[i].x, bl[i].y);
        }
    }
}

static constexpr int BUFW = 16512;   // words per weight buffer (frags + bias)

__device__ __forceinline__ void issue_stage_copy(uint32_t buf_addr,
                                                 const uint32_t* img,
                                                 const float* bias, int t) {
    #pragma unroll
    for (int i = 0; i < 16; i++)
        CP_ASYNC16(buf_addr + (t + 256 * i) * 16, img + (t + 256 * i) * 4);
    if (t < 32)
        CP_ASYNC16(buf_addr + 16384 * 4 + t * 16, bias + t * 4);
}

// ---------------------------------------------------------------------------
// Head kernel: A = ssp(x); mj = ssp(A@Wj+bj); v = ssp(A@Wi+bi)
// Both weight stages prefetched via cp.async before/during A-frag init.
// ---------------------------------------------------------------------------
static constexpr int HEAD_SMEM = 2 * BUFW * 4;

__global__ void __launch_bounds__(256, 1)
tc_head_kernel(const float* __restrict__ x,
               const float* __restrict__ bj, const float* __restrict__ bi,
               float* __restrict__ mj, float* __restrict__ v, int N) {
    extern __shared__ uint32_t sm[];
    const uint32_t sm_addr = smem_u32(sm);

    const int t = threadIdx.x, w = t >> 5, l = t & 31;
    const int g = l >> 2, m4 = l & 3;
    const int loff = l * 8;
    const int row_lo = blockIdx.x * 128 + w * 16 + g;
    const int row_hi = row_lo + 8;
    const int cb = 2 * m4;

    // prefetch Wj (slot 0) then Wi (slot 1); overlap with A-frag init
    issue_stage_copy(sm_addr, d_wimg, bj, t);
    CP_COMMIT();
    issue_stage_copy(sm_addr + BUFW * 4, d_wimg + 16384, bi, t);
    CP_COMMIT();

    uint32_t ahi[32], alo[32];
    #pragma unroll
    for (int nt = 0; nt < 16; nt++) {
        int c0 = nt * 8 + cb;
        float2 a = (row_lo < N) ? *reinterpret_cast<const float2*>(x + (size_t)row_lo * D + c0)
                                : make_float2(0.f, 0.f);
        float2 b = (row_hi < N) ? *reinterpret_cast<const float2*>(x + (size_t)row_hi * D + c0)
                                : make_float2(0.f, 0.f);
        int base = (nt >> 1) * 4 + (nt & 1) * 2;
        build_frag(sspf(a.x), sspf(a.y), ahi[base], alo[base]);
        build_frag(sspf(b.x), sspf(b.y), ahi[base + 1], alo[base + 1]);
    }

    #pragma unroll
    for (int s = 0; s < 2; s++) {
        if (s == 0) CP_WAIT1(); else CP_WAIT0();
        __syncthreads();

        const uint32_t* wbuf = sm + s * BUFW;
        const float* bias_s = reinterpret_cast<const float*>(wbuf + 16384);

        float acc[64];
        #pragma unroll
        for (int i = 0; i < 64; i++) acc[i] = 0.0f;
        stage_mma_smem(wbuf, loff, ahi, alo, acc);

        float* outp = s ? v : mj;
        #pragma unroll
        for (int nt = 0; nt < 16; nt++) {
            int c0 = nt * 8 + cb;
            float bv0 = bias_s[c0], bv1 = bias_s[c0 + 1];
            float s0 = sspf(acc[nt * 4 + 0] + bv0);
            float s1 = sspf(acc[nt * 4 + 1] + bv1);
            float s2 = sspf(acc[nt * 4 + 2] + bv0);
            float s3 = sspf(acc[nt * 4 + 3] + bv1);
            if (row_lo < N)
                *reinterpret_cast<float2*>(outp + (size_t)row_lo * D + c0) = make_float2(s0, s1);
            if (row_hi < N)
                *reinterpret_cast<float2*>(outp + (size_t)row_hi * D + c0) = make_float2(s2, s3);
        }
    }
}

// ---------------------------------------------------------------------------
// Tail kernel (R6 proven): register-chained, cp.async double-buffered weights
// ---------------------------------------------------------------------------
static constexpr int TAIL_SMEM = (2 * BUFW + 128) * 4;

__global__ void __launch_bounds__(256, 1)
tc_tail_kernel(const float* __restrict__ v_in, const float* __restrict__ x,
               const float* __restrict__ u,
               const float* __restrict__ rbint, const float* __restrict__ bf,
               const float* __restrict__ rbatm, const float* __restrict__ rbout,
               int n_int, int n_atom, int n_out,
               float* __restrict__ h_out, float* __restrict__ o_out, int N) {
    extern __shared__ uint32_t sm[];
    float* u_s = reinterpret_cast<float*>(sm + 2 * BUFW);
    const uint32_t sm_addr = smem_u32(sm);

    const int t = threadIdx.x, w = t >> 5, l = t & 31;
    const int g = l >> 2, m4 = l & 3;
    const int loff = l * 8;
    const int row_lo = blockIdx.x * 128 + w * 16 + g;
    const int row_hi = row_lo + 8;
    const int cb = 2 * m4;

    if (t < 32)
        reinterpret_cast<float4*>(u_s)[t] = reinterpret_cast<const float4*>(u)[t];

    const int total = 2 * n_int + 1 + 2 * n_atom + 2 * n_out;

    auto stage_desc = [&](int s, int& mat, const float*& bias, int& mode, bool& storeh) {
        storeh = false;
        if (s < 2 * n_int) {
            mat = 3 + (s >> 1); bias = rbint + (size_t)(s >> 1) * D;
            mode = (s & 1) ? 1 : 0;
        } else if (s == 2 * n_int) {
            mat = 2; bias = bf; mode = 2; storeh = (n_atom == 0);
        } else {
            int s2 = s - 2 * n_int - 1;
            if (s2 < 2 * n_atom) {
                mat = 3 + n_int + (s2 >> 1); bias = rbatm + (size_t)(s2 >> 1) * D;
                mode = (s2 & 1) ? 1 : 0;
                storeh = (s2 == 2 * n_atom - 1);
            } else {
                int s3 = s2 - 2 * n_atom;
                mat = 3 + n_int + n_atom + (s3 >> 1); bias = rbout + (size_t)(s3 >> 1) * D;
                mode = (s3 & 1) ? ((s3 == 2 * n_out - 1) ? 3 : 1) : 0;
            }
        }
    };

    {
        int mat; const float* bias; int mode; bool sh;
        stage_desc(0, mat, bias, mode, sh);
        issue_stage_copy(sm_addr, d_wimg + (size_t)mat * 16384, bias, t);
        CP_COMMIT();
    }

    float vr[64];
    uint32_t ahi[32], alo[32];
    #pragma unroll
    for (int nt = 0; nt < 16; nt++) {
        int c0 = nt * 8 + cb;
        float2 a = (row_lo < N) ? *reinterpret_cast<const float2*>(v_in + (size_t)row_lo * D + c0)
                                : make_float2(0.f, 0.f);
        float2 b = (row_hi < N) ? *reinterpret_cast<const float2*>(v_in + (size_t)row_hi * D + c0)
                                : make_float2(0.f, 0.f);
        vr[nt * 4 + 0] = a.x; vr[nt * 4 + 1] = a.y;
        vr[nt * 4 + 2] = b.x; vr[nt * 4 + 3] = b.y;
        int base = (nt >> 1) * 4 + (nt & 1) * 2;
        build_frag(sspf(a.x), sspf(a.y), ahi[base], alo[base]);
        build_frag(sspf(b.x), sspf(b.y), ahi[base + 1], alo[base + 1]);
    }

    for (int s = 0; s < total; s++) {
        int mat; const float* bias; int mode; bool storeh;
        stage_desc(s, mat, bias, mode, storeh);

        if (s + 1 < total) {
            int nmat; const float* nbias; int nmode; bool nsh;
            stage_desc(s + 1, nmat, nbias, nmode, nsh);
            issue_stage_copy(sm_addr + ((s + 1) & 1) * BUFW * 4,
                             d_wimg + (size_t)nmat * 16384, nbias, t);
        }
        CP_COMMIT();
        CP_WAIT1();
        __syncthreads();

        const uint32_t* wbuf = sm + (s & 1) * BUFW;
        const float* bias_s = reinterpret_cast<const float*>(wbuf + 16384);

        float acc[64];
        #pragma unroll
        for (int i = 0; i < 64; i++) acc[i] = 0.0f;
        stage_mma_smem(wbuf, loff, ahi, alo, acc);

        #pragma unroll
        for (int nt = 0; nt < 16; nt++) {
            int c0 = nt * 8 + cb;
            float bv0 = bias_s[c0], bv1 = bias_s[c0 + 1];
            float v0 = acc[nt * 4 + 0] + bv0;
            float v1 = acc[nt * 4 + 1] + bv1;
            float v2 = acc[nt * 4 + 2] + bv0;
            float v3 = acc[nt * 4 + 3] + bv1;
            if (mode == 1 || mode == 3) {
                v0 += vr[nt * 4 + 0]; v1 += vr[nt * 4 + 1];
                v2 += vr[nt * 4 + 2]; v3 += vr[nt * 4 + 3];
            }
            if (mode == 2) {
                float2 xl = (row_lo < N) ? *reinterpret_cast<const float2*>(x + (size_t)row_lo * D + c0)
                                         : make_float2(0.f, 0.f);
                float2 xh = (row_hi < N) ? *reinterpret_cast<const float2*>(x + (size_t)row_hi * D + c0)
                                         : make_float2(0.f, 0.f);
                float u0 = u_s[c0], u1 = u_s[c0 + 1];
                v0 += u0 * sspf(xl.x); v1 += u1 * sspf(xl.y);
                v2 += u0 * sspf(xh.x); v3 += u1 * sspf(xh.y);
            }
            if (mode == 1 || mode == 2) {
                vr[nt * 4 + 0] = v0; vr[nt * 4 + 1] = v1;
                vr[nt * 4 + 2] = v2; vr[nt * 4 + 3] = v3;
            }
            float s0 = sspf(v0), s1 = sspf(v1), s2 = sspf(v2), s3 = sspf(v3);
            if (mode == 3) {
                if (row_lo < N)
                    *reinterpret_cast<float2*>(o_out + (size_t)row_lo * D + c0) = make_float2(s0, s1);
                if (row_hi < N)
                    *reinterpret_cast<float2*>(o_out + (size_t)row_hi * D + c0) = make_float2(s2, s3);
            } else {
                int base = (nt >> 1) * 4 + (nt & 1) * 2;
                build_frag(s0, s1, ahi[base], alo[base]);
                build_frag(s2, s3, ahi[base + 1], alo[base + 1]);
            }
        }

        if (storeh) {
            #pragma unroll
            for (int nt = 0; nt < 16; nt++) {
                int c0 = nt * 8 + cb;
                if (row_lo < N)
                    *reinterpret_cast<float2*>(h_out + (size_t)row_lo * D + c0) =
                        make_float2(vr[nt * 4 + 0], vr[nt * 4 + 1]);
                if (row_hi < N)
                    *reinterpret_cast<float2*>(h_out + (size_t)row_hi * D + c0) =
                        make_float2(vr[nt * 4 + 2], vr[nt * 4 + 3]);
            }
        }
        __syncthreads();
    }
}

// ---------------------------------------------------------------------------
// Edge kernel: HMMA gate + row-major phases; persistent grid (Wg loaded once
// per block); scatter loop unrolled so ptxas front-batches the mj LDG.128s.
// ---------------------------------------------------------------------------
static constexpr int EDGE_SMEM = (4096 + 8 * 16 * 132) * 4;   // 84 KB

__device__ __forceinline__ void edge_scatter_one(const float* __restrict__ stag,
                                                 const float* __restrict__ mj,
                                                 float* __restrict__ v,
                                                 int r, int iv, int jv, int l) {
    int j = __shfl_sync(0xffffffffu, jv, r);
    int i = __shfl_sync(0xffffffffu, iv, r);
    float4 gt = *reinterpret_cast<const float4*>(stag + r * 132 + l * 4);
    float4 m  = __ldg(reinterpret_cast<const float4*>(mj + (size_t)j * D + l * 4));
    float x0 = gt.x * m.x, x1 = gt.y * m.y, x2 = gt.z * m.z, x3 = gt.w * m.w;
    asm volatile("red.global.add.v4.f32 [%0], {%1, %2, %3, %4};"
                 :: "l"(v + (size_t)i * D + l * 4),
                    "f"(x0), "f"(x1), "f"(x2), "f"(x3) : "memory");
}

__global__ void __launch_bounds__(256)
edge_mma_kernel(const float* __restrict__ g,
                const int* __restrict__ idx_i,
                const int* __restrict__ idx_j,
                const float* __restrict__ mj,
                float* __restrict__ v,
                int E, int wg_slot) {
    extern __shared__ uint32_t esm[];
    uint32_t* wgs = esm;                                  // 4096 words
    float* stag_all = reinterpret_cast<float*>(esm + 4096);

    {
        const uint4* src = reinterpret_cast<const uint4*>(d_wimg + (size_t)wg_slot * 16384);
        uint4* dst = reinterpret_cast<uint4*>(wgs);
        #pragma unroll
        for (int i = threadIdx.x; i < 1024; i += 256)
            dst[i] = src[i];
    }
    __syncthreads();

    const int t = threadIdx.x, l = t & 31, w = t >> 5;
    const int gq = l >> 2, m4 = l & 3;
    float* stag = stag_all + w * 16 * 132;
    const char* base = reinterpret_cast<const char*>(wgs);
    const int loff = l * 8;

    const int nbatches = (E + 15) / 16;
    for (int batch = blockIdx.x * 8 + w; batch < nbatches; batch += gridDim.x * 8) {
        const int e0 = batch * 16;
        const int nb = min(16, E - e0);

        // edge indices: lane l holds edge e0+l (l < nb)
        int iv = 0, jv = 0;
        if (l < nb) { iv = __ldg(idx_i + e0 + l); jv = __ldg(idx_j + e0 + l); }

        // stage g rows row-major (stride 132 floats)
        #pragma unroll
        for (int rr = 0; rr < 4; rr++) {
            int r = rr * 4 + (l >> 3);
            if (r < nb) {
                float4 gv = *reinterpret_cast<const float4*>(g + (size_t)(e0 + r) * 32 + (l & 7) * 4);
                *reinterpret_cast<float4*>(stag + r * 132 + (l & 7) * 4) = gv;
            }
        }
        __syncwarp();

        // build A-fragments from staged g (rows gq and 8+gq)
        uint32_t ahi[8], alo[8];
        #pragma unroll
        for (int kt = 0; kt < 2; kt++) {
            int kb = kt * 16 + 2 * m4;
            float2 p00 = (gq < nb)     ? *reinterpret_cast<const float2*>(stag + gq * 132 + kb)
                                       : make_float2(0.f, 0.f);
            float2 p01 = (gq < nb)     ? *reinterpret_cast<const float2*>(stag + gq * 132 + kb + 8)
                                       : make_float2(0.f, 0.f);
            float2 p10 = (8 + gq < nb) ? *reinterpret_cast<const float2*>(stag + (8 + gq) * 132 + kb)
                                       : make_float2(0.f, 0.f);
            float2 p11 = (8 + gq < nb) ? *reinterpret_cast<const float2*>(stag + (8 + gq) * 132 + kb + 8)
                                       : make_float2(0.f, 0.f);
            build_frag(p00.x, p00.y, ahi[kt * 4 + 0], alo[kt * 4 + 0]);
            build_frag(p10.x, p10.y, ahi[kt * 4 + 1], alo[kt * 4 + 1]);
            build_frag(p01.x, p01.y, ahi[kt * 4 + 2], alo[kt * 4 + 2]);
            build_frag(p11.x, p11.y, ahi[kt * 4 + 3], alo[kt * 4 + 3]);
        }
        __syncwarp();   // all lanes done reading g staging

        // gate[16,128] = g @ Wg  (bf16 split, fp32 acc)
        float acc[64];
        #pragma unroll
        for (int i = 0; i < 64; i++) acc[i] = 0.0f;

        #pragma unroll
        for (int nt = 0; nt < 16; nt++) {
            #pragma unroll
            for (int kt = 0; kt < 2; kt++) {
                uint2 bh = *reinterpret_cast<const uint2*>(base + (nt * 2 + kt) * 256 + loff);
                mma_bf16(acc + nt * 4, ahi + kt * 4, bh.x, bh.y);
                mma_bf16(acc + nt * 4, alo + kt * 4, bh.x, bh.y);
                uint2 bl = *reinterpret_cast<const uint2*>(base + 8192 + (nt * 2 + kt) * 256 + loff);
                mma_bf16(acc + nt * 4, ahi + kt * 4, bl.x, bl.y);
            }
        }

        // stage gate rows row-major (overwrites g staging)
        #pragma unroll
        for (int nt = 0; nt < 16; nt++) {
            int c0 = nt * 8 + 2 * m4;
            if (gq < nb)
                *reinterpret_cast<float2*>(stag + gq * 132 + c0) =
                    make_float2(acc[nt * 4 + 0], acc[nt * 4 + 1]);
            if (8 + gq < nb)
                *reinterpret_cast<float2*>(stag + (8 + gq) * 132 + c0) =
                    make_float2(acc[nt * 4 + 2], acc[nt * 4 + 3]);
        }
        __syncwarp();

        // per-edge FULL-ROW gather + scatter (unrolled fast path -> MLP 16)
        if (nb == 16) {
            #pragma unroll
            for (int r = 0; r < 16; r++)
                edge_scatter_one(stag, mj, v, r, iv, jv, l);
        } else {
            for (int r = 0; r < nb; r++)
                edge_scatter_one(stag, mj, v, r, iv, jv, l);
        }
        __syncwarp();   // staging reuse safety for next batch
    }
}

// ---------------------------------------------------------------------------
// Host-side dispatch
// ---------------------------------------------------------------------------
extern "C" void kernel_launch(void* const* d_in, const int* in_sizes, int n_in,
                              void* d_out, int out_size) {
    const float* x     = (const float*)d_in[0];
    const float* g_ij  = (const float*)d_in[1];
    const float* Wf    = (const float*)d_in[2];
    const float* bf    = (const float*)d_in[3];
    const float* Wg    = (const float*)d_in[4];
    const float* Wj    = (const float*)d_in[5];
    const float* bj    = (const float*)d_in[6];
    const float* Wi    = (const float*)d_in[7];
    const float* bi    = (const float*)d_in[8];
    const float* u     = (const float*)d_in[9];
    const float* rWint = (const float*)d_in[10];
    const float* rbint = (const float*)d_in[11];
    const float* rWatm = (const float*)d_in[12];
    const float* rbatm = (const float*)d_in[13];
    const float* rWout = (const float*)d_in[14];
    const float* rbout = (const float*)d_in[15];
    const int*   idx_i = (const int*)d_in[16];
    const int*   idx_j = (const int*)d_in[17];

    const int N      = in_sizes[0] / D;
    const int E      = in_sizes[16];
    const int n_int  = in_sizes[11] / D;
    const int n_atom = in_sizes[13] / D;
    const int n_out  = in_sizes[15] / D;

    if (N > MAXN) return;
    const int n_mats = 3 + n_int + n_atom + n_out;
    if (n_mats + 1 > MAXMATS) return;

    float *mj, *v;
    cudaGetSymbolAddress((void**)&mj, d_mj);
    cudaGetSymbolAddress((void**)&v,  d_v);

    float* o_out = (float*)d_out;                 // o -> first N*D
    float* h_out = (float*)d_out + (size_t)N * D; // h -> second N*D

    cudaFuncSetAttribute(tc_head_kernel, cudaFuncAttributeMaxDynamicSharedMemorySize, HEAD_SMEM);
    cudaFuncSetAttribute(tc_tail_kernel, cudaFuncAttributeMaxDynamicSharedMemorySize, TAIL_SMEM);
    cudaFuncSetAttribute(edge_mma_kernel, cudaFuncAttributeMaxDynamicSharedMemorySize, EDGE_SMEM);

    const int tiles = (N + 127) / 128;

    // 0) split + permute weights (incl. Wg at slot n_mats)
    wsplit_kernel<<<(n_mats + 1) * 8, 256>>>(Wj, Wi, Wf, rWint, rWatm, rWout, Wg,
                                             n_int, n_atom, n_out);

    // 1) mj = ssp(ssp(x)@Wj+bj); v = ssp(ssp(x)@Wi+bi)   [prefetched weights]
    tc_head_kernel<<<tiles, 256, HEAD_SMEM>>>(x, bj, bi, mj, v, N);

    // 2) v += segment_sum( (g_ij @ Wg) * mj[idx_j], idx_i )  [persistent grid]
    {
        int batches = (E + 15) / 16;
        int blocks  = (batches + 7) / 8;
        if (blocks > 592) blocks = 592;
        edge_mma_kernel<<<blocks, 256, EDGE_SMEM>>>(g_ij, idx_i, idx_j, mj, v, E, n_mats);
    }

    // 3) fused register-chained tail (R6 design)
    tc_tail_kernel<<<tiles, 256, TAIL_SMEM>>>(
        v, x, u, rbint, bf, rbatm, rbout, n_int, n_atom, n_out, h_out, o_out, N);
}

// round 16
// speedup vs baseline: 1.1969x; 1.0046x over previous
#include <cuda_runtime.h>
#include <cuda_bf16.h>
#include <math.h>
#include <stdint.h>

#define D 128
static constexpr int MAXN = 51200;
static constexpr int MAXMATS = 16;   // slots; last used slot holds Wg frags

// ---------------------------------------------------------------------------
// Scratch (no allocs allowed -> device globals)
// ---------------------------------------------------------------------------
__device__ float d_mj[MAXN * D];
__device__ float d_v [MAXN * D];
__device__ __align__(16) uint32_t d_wimg[MAXMATS * 16384];

__device__ __forceinline__ float sspf(float x) {
    return fmaxf(x, 0.0f) + __logf(1.0f + __expf(-fabsf(x))) - 0.69314718055994530942f;
}

// ---------------------------------------------------------------------------
// HMMA m16n8k16 bf16 (base PTX) + frag building
// ---------------------------------------------------------------------------
__device__ __forceinline__ void mma_bf16(float* d, const uint32_t* a,
                                         uint32_t b0, uint32_t b1) {
    asm volatile(
        "mma.sync.aligned.m16n8k16.row.col.f32.bf16.bf16.f32 "
        "{%0,%1,%2,%3}, {%4,%5,%6,%7}, {%8,%9}, {%0,%1,%2,%3};"
        : "+f"(d[0]), "+f"(d[1]), "+f"(d[2]), "+f"(d[3])
        : "r"(a[0]), "r"(a[1]), "r"(a[2]), "r"(a[3]), "r"(b0), "r"(b1));
}

__device__ __forceinline__ void build_frag(float s0, float s1,
                                           uint32_t& hi, uint32_t& lo) {
    __nv_bfloat162 h2 = __floats2bfloat162_rn(s0, s1);
    float l0 = s0 - __bfloat162float(h2.x);
    float l1 = s1 - __bfloat162float(h2.y);
    __nv_bfloat162 l2 = __floats2bfloat162_rn(l0, l1);
    hi = *reinterpret_cast<uint32_t*>(&h2);
    lo = *reinterpret_cast<uint32_t*>(&l2);
}

// ---------------------------------------------------------------------------
// cp.async + mbarrier helpers
// ---------------------------------------------------------------------------
__device__ __forceinline__ uint32_t smem_u32(const void* p) {
    uint32_t a;
    asm("{ .reg .u64 t; cvta.to.shared.u64 t, %1; cvt.u32.u64 %0, t; }"
        : "=r"(a) : "l"(p));
    return a;
}
#define CP_ASYNC16(dst, src) \
    asm volatile("cp.async.cg.shared.global [%0], [%1], 16;" :: "r"(dst), "l"(src))
#define CP_COMMIT() asm volatile("cp.async.commit_group;" ::: "memory")
#define CP_WAIT1()  asm volatile("cp.async.wait_group 1;"  ::: "memory")
#define CP_WAIT0()  asm volatile("cp.async.wait_group 0;"  ::: "memory")
#define CP_MBAR_ARRIVE(mb) \
    asm volatile("cp.async.mbarrier.arrive.noinc.shared.b64 [%0];" :: "r"(mb) : "memory")
#define MBAR_INIT(mb, c) \
    asm volatile("mbarrier.init.shared.b64 [%0], %1;" :: "r"(mb), "r"(c) : "memory")
#define MBAR_ARRIVE(mb) \
    asm volatile("mbarrier.arrive.shared.b64 _, [%0];" :: "r"(mb) : "memory")
#define MBAR_WAIT(mb, ph) do {                                                   \
    uint32_t _mb = (mb); uint32_t _p = (ph); uint32_t _done;                     \
    asm volatile("{\n\t.reg .pred p;\n\t"                                        \
        "mbarrier.try_wait.parity.shared.b64 p, [%1], %2;\n\t"                   \
        "selp.b32 %0, 1, 0, p;\n\t}"                                             \
        : "=r"(_done) : "r"(_mb), "r"(_p) : "memory");                           \
    if (!_done) {                                                                \
        asm volatile("{\n\t.reg .pred P1;\n\t"                                   \
            "WL_%=:\n\t"                                                         \
            "mbarrier.try_wait.parity.shared.b64 P1, [%0], %1;\n\t"              \
            "@P1 bra.uni WD_%=;\n\t"                                             \
            "bra.uni WL_%=;\n\t"                                                 \
            "WD_%=:\n\t}"                                                        \
            :: "r"(_mb), "r"(_p) : "memory");                                    \
    }                                                                            \
} while (0)

// ---------------------------------------------------------------------------
// Weight precompute (8 blocks per matrix)
// ---------------------------------------------------------------------------
__global__ void wsplit_kernel(const float* __restrict__ Wj,
                              const float* __restrict__ Wi,
                              const float* __restrict__ Wf,
                              const float* __restrict__ rWint,
                              const float* __restrict__ rWatm,
                              const float* __restrict__ rWout,
                              const float* __restrict__ Wg,
                              int n_int, int n_atom, int n_out) {
    int m    = blockIdx.x >> 3;
    int part = blockIdx.x & 7;
    int n_mats = 3 + n_int + n_atom + n_out;

    if (m == n_mats) {  // Wg [32 x 128]
        uint32_t* hi = d_wimg + (size_t)m * 16384;
        uint32_t* lo = hi + 2048;
        for (int idx = part * 256 + threadIdx.x; idx < 2048; idx += 2048) {
            int ri = idx & 1;
            int l  = (idx >> 1) & 31;
            int f  = idx >> 6;
            int kt = f & 1, nt = f >> 1;
            int n  = nt * 8 + (l >> 2);
            int k0 = kt * 16 + 2 * (l & 3) + ri * 8;
            uint32_t h, lw;
            build_frag(Wg[k0 * D + n], Wg[(k0 + 1) * D + n], h, lw);
            hi[idx] = h;
            lo[idx] = lw;
        }
        return;
    }

    const float* src;
    if (m == 0)                      src = Wj;
    else if (m == 1)                 src = Wi;
    else if (m == 2)                 src = Wf;
    else if (m < 3 + n_int)          src = rWint + (size_t)(m - 3) * D * D;
    else if (m < 3 + n_int + n_atom) src = rWatm + (size_t)(m - 3 - n_int) * D * D;
    else                             src = rWout + (size_t)(m - 3 - n_int - n_atom) * D * D;

    uint32_t* hi = d_wimg + (size_t)m * 16384;
    uint32_t* lo = hi + 8192;

    for (int idx = part * 1024 + threadIdx.x; idx < (part + 1) * 1024; idx += 256) {
        int ri = idx & 1;
        int l  = (idx >> 1) & 31;
        int f  = idx >> 6;
        int kt = f & 7, nt = f >> 3;
        int n  = nt * 8 + (l >> 2);
        int k0 = kt * 16 + 2 * (l & 3) + ri * 8;
        uint32_t h, lw;
        build_frag(src[k0 * D + n], src[(k0 + 1) * D + n], h, lw);
        hi[idx] = h;
        lo[idx] = lw;
    }
}

// ---------------------------------------------------------------------------
// MMA stage with B in smem: pass-separated, 4-nt register chunks.
// ---------------------------------------------------------------------------
__device__ __forceinline__ void stage_mma_smem(const uint32_t* wsm, int loff,
                                               const uint32_t* ahi, const uint32_t* alo,
                                               float* acc) {
    const char* base = reinterpret_cast<const char*>(wsm);
    #pragma unroll
    for (int kt = 0; kt < 8; kt++) {
        #pragma unroll
        for (int c = 0; c < 4; c++) {
            uint2 bh[4], bl[4];
            #pragma unroll
            for (int i = 0; i < 4; i++)
                bh[i] = *reinterpret_cast<const uint2*>(base + ((c * 4 + i) * 8 + kt) * 256 + loff);
            #pragma unroll
            for (int i = 0; i < 4; i++)
                bl[i] = *reinterpret_cast<const uint2*>(base + 32768 + ((c * 4 + i) * 8 + kt) * 256 + loff);
            #pragma unroll
            for (int i = 0; i < 4; i++)
                mma_bf16(acc + (c * 4 + i) * 4, ahi + kt * 4, bh[i].x, bh[i].y);
            #pragma unroll
            for (int i = 0; i < 4; i++)
                mma_bf16(acc + (c * 4 + i) * 4, alo + kt * 4, bh[i].x, bh[i].y);
            #pragma unroll
            for (int i = 0; i < 4; i++)
                mma_bf16(acc + (c * 4 + i) * 4, ahi + kt * 4, bl[i].x, bl[i].y);
        }
    }
}

static constexpr int BUFW = 16512;   // words per weight buffer (frags + bias)

__device__ __forceinline__ void issue_stage_copy(uint32_t buf_addr,
                                                 const uint32_t* img,
                                                 const float* bias, int t) {
    #pragma unroll
    for (int i = 0; i < 16; i++)
        CP_ASYNC16(buf_addr + (t + 256 * i) * 16, img + (t + 256 * i) * 4);
    if (t < 32)
        CP_ASYNC16(buf_addr + 16384 * 4 + t * 16, bias + t * 4);
}

// ---------------------------------------------------------------------------
// Head kernel: A = ssp(x); mj = ssp(A@Wj+bj); v = ssp(A@Wi+bi)
// Both weight stages prefetched via cp.async before/during A-frag init.
// ---------------------------------------------------------------------------
static constexpr int HEAD_SMEM = 2 * BUFW * 4;

__global__ void __launch_bounds__(256, 1)
tc_head_kernel(const float* __restrict__ x,
               const float* __restrict__ bj, const float* __restrict__ bi,
               float* __restrict__ mj, float* __restrict__ v, int N) {
    extern __shared__ uint32_t sm[];
    const uint32_t sm_addr = smem_u32(sm);

    const int t = threadIdx.x, w = t >> 5, l = t & 31;
    const int g = l >> 2, m4 = l & 3;
    const int loff = l * 8;
    const int row_lo = blockIdx.x * 128 + w * 16 + g;
    const int row_hi = row_lo + 8;
    const int cb = 2 * m4;

    issue_stage_copy(sm_addr, d_wimg, bj, t);
    CP_COMMIT();
    issue_stage_copy(sm_addr + BUFW * 4, d_wimg + 16384, bi, t);
    CP_COMMIT();

    uint32_t ahi[32], alo[32];
    #pragma unroll
    for (int nt = 0; nt < 16; nt++) {
        int c0 = nt * 8 + cb;
        float2 a = (row_lo < N) ? *reinterpret_cast<const float2*>(x + (size_t)row_lo * D + c0)
                                : make_float2(0.f, 0.f);
        float2 b = (row_hi < N) ? *reinterpret_cast<const float2*>(x + (size_t)row_hi * D + c0)
                                : make_float2(0.f, 0.f);
        int base = (nt >> 1) * 4 + (nt & 1) * 2;
        build_frag(sspf(a.x), sspf(a.y), ahi[base], alo[base]);
        build_frag(sspf(b.x), sspf(b.y), ahi[base + 1], alo[base + 1]);
    }

    #pragma unroll
    for (int s = 0; s < 2; s++) {
        if (s == 0) CP_WAIT1(); else CP_WAIT0();
        __syncthreads();

        const uint32_t* wbuf = sm + s * BUFW;
        const float* bias_s = reinterpret_cast<const float*>(wbuf + 16384);

        float acc[64];
        #pragma unroll
        for (int i = 0; i < 64; i++) acc[i] = 0.0f;
        stage_mma_smem(wbuf, loff, ahi, alo, acc);

        float* outp = s ? v : mj;
        #pragma unroll
        for (int nt = 0; nt < 16; nt++) {
            int c0 = nt * 8 + cb;
            float bv0 = bias_s[c0], bv1 = bias_s[c0 + 1];
            float s0 = sspf(acc[nt * 4 + 0] + bv0);
            float s1 = sspf(acc[nt * 4 + 1] + bv1);
            float s2 = sspf(acc[nt * 4 + 2] + bv0);
            float s3 = sspf(acc[nt * 4 + 3] + bv1);
            if (row_lo < N)
                *reinterpret_cast<float2*>(outp + (size_t)row_lo * D + c0) = make_float2(s0, s1);
            if (row_hi < N)
                *reinterpret_cast<float2*>(outp + (size_t)row_hi * D + c0) = make_float2(s2, s3);
        }
    }
}

// ---------------------------------------------------------------------------
// Tail kernel: register-chained stages; 3-deep mbarrier ring for weights —
// NO block barriers, so warps skew and one warp's HMMA/LDS overlaps another
// warp's MUFU/FMA epilogue.
// full[k]: 256 x cp.async.mbarrier.arrive.noinc (copies landed)
// empty[k]: 256 x mbarrier.arrive (readers done)
// ---------------------------------------------------------------------------
static constexpr int TAIL_SMEM = 3 * BUFW * 4 + 64;

__global__ void __launch_bounds__(256, 1)
tc_tail_kernel(const float* __restrict__ v_in, const float* __restrict__ x,
               const float* __restrict__ u,
               const float* __restrict__ rbint, const float* __restrict__ bf,
               const float* __restrict__ rbatm, const float* __restrict__ rbout,
               int n_int, int n_atom, int n_out,
               float* __restrict__ h_out, float* __restrict__ o_out, int N) {
    extern __shared__ uint32_t sm[];
    const uint32_t sm_addr = smem_u32(sm);
    const uint32_t mb_full  = sm_addr + 3 * BUFW * 4;
    const uint32_t mb_empty = mb_full + 24;

    const int t = threadIdx.x, w = t >> 5, l = t & 31;
    const int g = l >> 2, m4 = l & 3;
    const int loff = l * 8;
    const int row_lo = blockIdx.x * 128 + w * 16 + g;
    const int row_hi = row_lo + 8;
    const int cb = 2 * m4;

    if (t < 3) {
        MBAR_INIT(mb_full + t * 8, 256);
        MBAR_INIT(mb_empty + t * 8, 256);
    }
    __syncthreads();

    const int total = 2 * n_int + 1 + 2 * n_atom + 2 * n_out;

    auto stage_desc = [&](int s, int& mat, const float*& bias, int& mode, bool& storeh) {
        storeh = false;
        if (s < 2 * n_int) {
            mat = 3 + (s >> 1); bias = rbint + (size_t)(s >> 1) * D;
            mode = (s & 1) ? 1 : 0;
        } else if (s == 2 * n_int) {
            mat = 2; bias = bf; mode = 2; storeh = (n_atom == 0);
        } else {
            int s2 = s - 2 * n_int - 1;
            if (s2 < 2 * n_atom) {
                mat = 3 + n_int + (s2 >> 1); bias = rbatm + (size_t)(s2 >> 1) * D;
                mode = (s2 & 1) ? 1 : 0;
                storeh = (s2 == 2 * n_atom - 1);
            } else {
                int s3 = s2 - 2 * n_atom;
                mat = 3 + n_int + n_atom + (s3 >> 1); bias = rbout + (size_t)(s3 >> 1) * D;
                mode = (s3 & 1) ? ((s3 == 2 * n_out - 1) ? 3 : 1) : 0;
            }
        }
    };

    // prologue: prefetch stages 0 and 1
    for (int d = 0; d < 2 && d < total; d++) {
        int mat; const float* bias; int mode; bool sh;
        stage_desc(d, mat, bias, mode, sh);
        issue_stage_copy(sm_addr + (uint32_t)d * BUFW * 4,
                         d_wimg + (size_t)mat * 16384, bias, t);
        CP_MBAR_ARRIVE(mb_full + d * 8);
    }

    // init fragments + residual carry
    float vr[64];
    uint32_t ahi[32], alo[32];
    #pragma unroll
    for (int nt = 0; nt < 16; nt++) {
        int c0 = nt * 8 + cb;
        float2 a = (row_lo < N) ? *reinterpret_cast<const float2*>(v_in + (size_t)row_lo * D + c0)
                                : make_float2(0.f, 0.f);
        float2 b = (row_hi < N) ? *reinterpret_cast<const float2*>(v_in + (size_t)row_hi * D + c0)
                                : make_float2(0.f, 0.f);
        vr[nt * 4 + 0] = a.x; vr[nt * 4 + 1] = a.y;
        vr[nt * 4 + 2] = b.x; vr[nt * 4 + 3] = b.y;
        int base = (nt >> 1) * 4 + (nt & 1) * 2;
        build_frag(sspf(a.x), sspf(a.y), ahi[base], alo[base]);
        build_frag(sspf(b.x), sspf(b.y), ahi[base + 1], alo[base + 1]);
    }

    for (int s = 0; s < total; s++) {
        // prefetch stage s+2 into ring slot (s+2)%3
        int pf = s + 2;
        if (pf < total) {
            if (pf >= 3)
                MBAR_WAIT(mb_empty + (pf % 3) * 8, ((pf - 3) / 3) & 1);
            int pmat; const float* pbias; int pmode; bool psh;
            stage_desc(pf, pmat, pbias, pmode, psh);
            issue_stage_copy(sm_addr + (uint32_t)(pf % 3) * BUFW * 4,
                             d_wimg + (size_t)pmat * 16384, pbias, t);
            CP_MBAR_ARRIVE(mb_full + (pf % 3) * 8);
        }

        int mat; const float* bias; int mode; bool storeh;
        stage_desc(s, mat, bias, mode, storeh);

        MBAR_WAIT(mb_full + (s % 3) * 8, (s / 3) & 1);

        const uint32_t* wbuf = sm + (s % 3) * BUFW;
        const float* bias_s = reinterpret_cast<const float*>(wbuf + 16384);

        float acc[64];
        #pragma unroll
        for (int i = 0; i < 64; i++) acc[i] = 0.0f;
        stage_mma_smem(wbuf, loff, ahi, alo, acc);

        #pragma unroll
        for (int nt = 0; nt < 16; nt++) {
            int c0 = nt * 8 + cb;
            float bv0 = bias_s[c0], bv1 = bias_s[c0 + 1];
            float v0 = acc[nt * 4 + 0] + bv0;
            float v1 = acc[nt * 4 + 1] + bv1;
            float v2 = acc[nt * 4 + 2] + bv0;
            float v3 = acc[nt * 4 + 3] + bv1;
            if (mode == 1 || mode == 3) {
                v0 += vr[nt * 4 + 0]; v1 += vr[nt * 4 + 1];
                v2 += vr[nt * 4 + 2]; v3 += vr[nt * 4 + 3];
            }
            if (mode == 2) {
                float2 xl = (row_lo < N) ? *reinterpret_cast<const float2*>(x + (size_t)row_lo * D + c0)
                                         : make_float2(0.f, 0.f);
                float2 xh = (row_hi < N) ? *reinterpret_cast<const float2*>(x + (size_t)row_hi * D + c0)
                                         : make_float2(0.f, 0.f);
                float2 uv = __ldg(reinterpret_cast<const float2*>(u + c0));
                v0 += uv.x * sspf(xl.x); v1 += uv.y * sspf(xl.y);
                v2 += uv.x * sspf(xh.x); v3 += uv.y * sspf(xh.y);
            }
            if (mode == 1 || mode == 2) {
                vr[nt * 4 + 0] = v0; vr[nt * 4 + 1] = v1;
                vr[nt * 4 + 2] = v2; vr[nt * 4 + 3] = v3;
            }
            float s0 = sspf(v0), s1 = sspf(v1), s2 = sspf(v2), s3 = sspf(v3);
            if (mode == 3) {
                if (row_lo < N)
                    *reinterpret_cast<float2*>(o_out + (size_t)row_lo * D + c0) = make_float2(s0, s1);
                if (row_hi < N)
                    *reinterpret_cast<float2*>(o_out + (size_t)row_hi * D + c0) = make_float2(s2, s3);
            } else {
                int base = (nt >> 1) * 4 + (nt & 1) * 2;
                build_frag(s0, s1, ahi[base], alo[base]);
                build_frag(s2, s3, ahi[base + 1], alo[base + 1]);
            }
        }

        MBAR_ARRIVE(mb_empty + (s % 3) * 8);

        if (storeh) {
            #pragma unroll
            for (int nt = 0; nt < 16; nt++) {
                int c0 = nt * 8 + cb;
                if (row_lo < N)
                    *reinterpret_cast<float2*>(h_out + (size_t)row_lo * D + c0) =
                        make_float2(vr[nt * 4 + 0], vr[nt * 4 + 1]);
                if (row_hi < N)
                    *reinterpret_cast<float2*>(h_out + (size_t)row_hi * D + c0) =
                        make_float2(vr[nt * 4 + 2], vr[nt * 4 + 3]);
            }
        }
    }
}

// ---------------------------------------------------------------------------
// Edge kernel: HMMA gate + row-major phases; persistent grid; unrolled scatter
// ---------------------------------------------------------------------------
static constexpr int EDGE_SMEM = (4096 + 8 * 16 * 132) * 4;   // 84 KB

__device__ __forceinline__ void edge_scatter_one(const float* __restrict__ stag,
                                                 const float* __restrict__ mj,
                                                 float* __restrict__ v,
                                                 int r, int iv, int jv, int l) {
    int j = __shfl_sync(0xffffffffu, jv, r);
    int i = __shfl_sync(0xffffffffu, iv, r);
    float4 gt = *reinterpret_cast<const float4*>(stag + r * 132 + l * 4);
    float4 m  = __ldg(reinterpret_cast<const float4*>(mj + (size_t)j * D + l * 4));
    float x0 = gt.x * m.x, x1 = gt.y * m.y, x2 = gt.z * m.z, x3 = gt.w * m.w;
    asm volatile("red.global.add.v4.f32 [%0], {%1, %2, %3, %4};"
                 :: "l"(v + (size_t)i * D + l * 4),
                    "f"(x0), "f"(x1), "f"(x2), "f"(x3) : "memory");
}

__global__ void __launch_bounds__(256)
edge_mma_kernel(const float* __restrict__ g,
                const int* __restrict__ idx_i,
                const int* __restrict__ idx_j,
                const float* __restrict__ mj,
                float* __restrict__ v,
                int E, int wg_slot) {
    extern __shared__ uint32_t esm[];
    uint32_t* wgs = esm;                                  // 4096 words
    float* stag_all = reinterpret_cast<float*>(esm + 4096);

    {
        const uint4* src = reinterpret_cast<const uint4*>(d_wimg + (size_t)wg_slot * 16384);
        uint4* dst = reinterpret_cast<uint4*>(wgs);
        #pragma unroll
        for (int i = threadIdx.x; i < 1024; i += 256)
            dst[i] = src[i];
    }
    __syncthreads();

    const int t = threadIdx.x, l = t & 31, w = t >> 5;
    const int gq = l >> 2, m4 = l & 3;
    float* stag = stag_all + w * 16 * 132;
    const char* base = reinterpret_cast<const char*>(wgs);
    const int loff = l * 8;

    const int nbatches = (E + 15) / 16;
    for (int batch = blockIdx.x * 8 + w; batch < nbatches; batch += gridDim.x * 8) {
        const int e0 = batch * 16;
        const int nb = min(16, E - e0);

        int iv = 0, jv = 0;
        if (l < nb) { iv = __ldg(idx_i + e0 + l); jv = __ldg(idx_j + e0 + l); }

        #pragma unroll
        for (int rr = 0; rr < 4; rr++) {
            int r = rr * 4 + (l >> 3);
            if (r < nb) {
                float4 gv = *reinterpret_cast<const float4*>(g + (size_t)(e0 + r) * 32 + (l & 7) * 4);
                *reinterpret_cast<float4*>(stag + r * 132 + (l & 7) * 4) = gv;
            }
        }
        __syncwarp();

        uint32_t ahi[8], alo[8];
        #pragma unroll
        for (int kt = 0; kt < 2; kt++) {
            int kb = kt * 16 + 2 * m4;
            float2 p00 = (gq < nb)     ? *reinterpret_cast<const float2*>(stag + gq * 132 + kb)
                                       : make_float2(0.f, 0.f);
            float2 p01 = (gq < nb)     ? *reinterpret_cast<const float2*>(stag + gq * 132 + kb + 8)
                                       : make_float2(0.f, 0.f);
            float2 p10 = (8 + gq < nb) ? *reinterpret_cast<const float2*>(stag + (8 + gq) * 132 + kb)
                                       : make_float2(0.f, 0.f);
            float2 p11 = (8 + gq < nb) ? *reinterpret_cast<const float2*>(stag + (8 + gq) * 132 + kb + 8)
                                       : make_float2(0.f, 0.f);
            build_frag(p00.x, p00.y, ahi[kt * 4 + 0], alo[kt * 4 + 0]);
            build_frag(p10.x, p10.y, ahi[kt * 4 + 1], alo[kt * 4 + 1]);
            build_frag(p01.x, p01.y, ahi[kt * 4 + 2], alo[kt * 4 + 2]);
            build_frag(p11.x, p11.y, ahi[kt * 4 + 3], alo[kt * 4 + 3]);
        }
        __syncwarp();

        float acc[64];
        #pragma unroll
        for (int i = 0; i < 64; i++) acc[i] = 0.0f;

        #pragma unroll
        for (int nt = 0; nt < 16; nt++) {
            #pragma unroll
            for (int kt = 0; kt < 2; kt++) {
                uint2 bh = *reinterpret_cast<const uint2*>(base + (nt * 2 + kt) * 256 + loff);
                mma_bf16(acc + nt * 4, ahi + kt * 4, bh.x, bh.y);
                mma_bf16(acc + nt * 4, alo + kt * 4, bh.x, bh.y);
                uint2 bl = *reinterpret_cast<const uint2*>(base + 8192 + (nt * 2 + kt) * 256 + loff);
                mma_bf16(acc + nt * 4, ahi + kt * 4, bl.x, bl.y);
            }
        }

        #pragma unroll
        for (int nt = 0; nt < 16; nt++) {
            int c0 = nt * 8 + 2 * m4;
            if (gq < nb)
                *reinterpret_cast<float2*>(stag + gq * 132 + c0) =
                    make_float2(acc[nt * 4 + 0], acc[nt * 4 + 1]);
            if (8 + gq < nb)
                *reinterpret_cast<float2*>(stag + (8 + gq) * 132 + c0) =
                    make_float2(acc[nt * 4 + 2], acc[nt * 4 + 3]);
        }
        __syncwarp();

        if (nb == 16) {
            #pragma unroll
            for (int r = 0; r < 16; r++)
                edge_scatter_one(stag, mj, v, r, iv, jv, l);
        } else {
            for (int r = 0; r < nb; r++)
                edge_scatter_one(stag, mj, v, r, iv, jv, l);
        }
        __syncwarp();
    }
}

// ---------------------------------------------------------------------------
// Host-side dispatch
// ---------------------------------------------------------------------------
extern "C" void kernel_launch(void* const* d_in, const int* in_sizes, int n_in,
                              void* d_out, int out_size) {
    const float* x     = (const float*)d_in[0];
    const float* g_ij  = (const float*)d_in[1];
    const float* Wf    = (const float*)d_in[2];
    const float* bf    = (const float*)d_in[3];
    const float* Wg    = (const float*)d_in[4];
    const float* Wj    = (const float*)d_in[5];
    const float* bj    = (const float*)d_in[6];
    const float* Wi    = (const float*)d_in[7];
    const float* bi    = (const float*)d_in[8];
    const float* u     = (const float*)d_in[9];
    const float* rWint = (const float*)d_in[10];
    const float* rbint = (const float*)d_in[11];
    const float* rWatm = (const float*)d_in[12];
    const float* rbatm = (const float*)d_in[13];
    const float* rWout = (const float*)d_in[14];
    const float* rbout = (const float*)d_in[15];
    const int*   idx_i = (const int*)d_in[16];
    const int*   idx_j = (const int*)d_in[17];

    const int N      = in_sizes[0] / D;
    const int E      = in_sizes[16];
    const int n_int  = in_sizes[11] / D;
    const int n_atom = in_sizes[13] / D;
    const int n_out  = in_sizes[15] / D;

    if (N > MAXN) return;
    const int n_mats = 3 + n_int + n_atom + n_out;
    if (n_mats + 1 > MAXMATS) return;

    float *mj, *v;
    cudaGetSymbolAddress((void**)&mj, d_mj);
    cudaGetSymbolAddress((void**)&v,  d_v);

    float* o_out = (float*)d_out;                 // o -> first N*D
    float* h_out = (float*)d_out + (size_t)N * D; // h -> second N*D

    cudaFuncSetAttribute(tc_head_kernel, cudaFuncAttributeMaxDynamicSharedMemorySize, HEAD_SMEM);
    cudaFuncSetAttribute(tc_tail_kernel, cudaFuncAttributeMaxDynamicSharedMemorySize, TAIL_SMEM);
    cudaFuncSetAttribute(edge_mma_kernel, cudaFuncAttributeMaxDynamicSharedMemorySize, EDGE_SMEM);

    const int tiles = (N + 127) / 128;

    // 0) split + permute weights (incl. Wg at slot n_mats)
    wsplit_kernel<<<(n_mats + 1) * 8, 256>>>(Wj, Wi, Wf, rWint, rWatm, rWout, Wg,
                                             n_int, n_atom, n_out);

    // 1) mj = ssp(ssp(x)@Wj+bj); v = ssp(ssp(x)@Wi+bi)
    tc_head_kernel<<<tiles, 256, HEAD_SMEM>>>(x, bj, bi, mj, v, N);

    // 2) v += segment_sum( (g_ij @ Wg) * mj[idx_j], idx_i )
    {
        int batches = (E + 15) / 16;
        int blocks  = (batches + 7) / 8;
        if (blocks > 592) blocks = 592;
        edge_mma_kernel<<<blocks, 256, EDGE_SMEM>>>(g_ij, idx_i, idx_j, mj, v, E, n_mats);
    }

    // 3) fused tail with barrier-free mbarrier ring
    tc_tail_kernel<<<tiles, 256, TAIL_SMEM>>>(
        v, x, u, rbint, bf, rbatm, rbout, n_int, n_atom, n_out, h_out, o_out, N);
}

// round 17
// speedup vs baseline: 1.2008x; 1.0032x over previous
#include <cuda_runtime.h>
#include <cuda_bf16.h>
#include <math.h>
#include <stdint.h>

#define D 128
static constexpr int MAXN = 51200;
static constexpr int MAXMATS = 16;   // slots; last used slot holds Wg frags

// ---------------------------------------------------------------------------
// Scratch (no allocs allowed -> device globals)
// ---------------------------------------------------------------------------
__device__ float d_mj[MAXN * D];
__device__ float d_v [MAXN * D];
__device__ __align__(16) uint32_t d_wimg[MAXMATS * 16384];

__device__ __forceinline__ float sspf(float x) {
    return fmaxf(x, 0.0f) + __logf(1.0f + __expf(-fabsf(x))) - 0.69314718055994530942f;
}

// ---------------------------------------------------------------------------
// HMMA m16n8k16 bf16 (base PTX) + frag building
// ---------------------------------------------------------------------------
__device__ __forceinline__ void mma_bf16(float* d, const uint32_t* a,
                                         uint32_t b0, uint32_t b1) {
    asm volatile(
        "mma.sync.aligned.m16n8k16.row.col.f32.bf16.bf16.f32 "
        "{%0,%1,%2,%3}, {%4,%5,%6,%7}, {%8,%9}, {%0,%1,%2,%3};"
        : "+f"(d[0]), "+f"(d[1]), "+f"(d[2]), "+f"(d[3])
        : "r"(a[0]), "r"(a[1]), "r"(a[2]), "r"(a[3]), "r"(b0), "r"(b1));
}

__device__ __forceinline__ void build_frag(float s0, float s1,
                                           uint32_t& hi, uint32_t& lo) {
    __nv_bfloat162 h2 = __floats2bfloat162_rn(s0, s1);
    float l0 = s0 - __bfloat162float(h2.x);
    float l1 = s1 - __bfloat162float(h2.y);
    __nv_bfloat162 l2 = __floats2bfloat162_rn(l0, l1);
    hi = *reinterpret_cast<uint32_t*>(&h2);
    lo = *reinterpret_cast<uint32_t*>(&l2);
}

// ---------------------------------------------------------------------------
// cp.async + mbarrier helpers
// ---------------------------------------------------------------------------
__device__ __forceinline__ uint32_t smem_u32(const void* p) {
    uint32_t a;
    asm("{ .reg .u64 t; cvta.to.shared.u64 t, %1; cvt.u32.u64 %0, t; }"
        : "=r"(a) : "l"(p));
    return a;
}
#define CP_ASYNC16(dst, src) \
    asm volatile("cp.async.cg.shared.global [%0], [%1], 16;" :: "r"(dst), "l"(src))
#define CP_COMMIT() asm volatile("cp.async.commit_group;" ::: "memory")
#define CP_WAIT1()  asm volatile("cp.async.wait_group 1;"  ::: "memory")
#define CP_WAIT0()  asm volatile("cp.async.wait_group 0;"  ::: "memory")
#define CP_MBAR_ARRIVE(mb) \
    asm volatile("cp.async.mbarrier.arrive.noinc.shared.b64 [%0];" :: "r"(mb) : "memory")
#define MBAR_INIT(mb, c) \
    asm volatile("mbarrier.init.shared.b64 [%0], %1;" :: "r"(mb), "r"(c) : "memory")
#define MBAR_ARRIVE(mb) \
    asm volatile("mbarrier.arrive.shared.b64 _, [%0];" :: "r"(mb) : "memory")
#define MBAR_WAIT(mb, ph) do {                                                   \
    uint32_t _mb = (mb); uint32_t _p = (ph); uint32_t _done;                     \
    asm volatile("{\n\t.reg .pred p;\n\t"                                        \
        "mbarrier.try_wait.parity.shared.b64 p, [%1], %2;\n\t"                   \
        "selp.b32 %0, 1, 0, p;\n\t}"                                             \
        : "=r"(_done) : "r"(_mb), "r"(_p) : "memory");                           \
    if (!_done) {                                                                \
        asm volatile("{\n\t.reg .pred P1;\n\t"                                   \
            "WL_%=:\n\t"                                                         \
            "mbarrier.try_wait.parity.shared.b64 P1, [%0], %1;\n\t"              \
            "@P1 bra.uni WD_%=;\n\t"                                             \
            "bra.uni WL_%=;\n\t"                                                 \
            "WD_%=:\n\t}"                                                        \
            :: "r"(_mb), "r"(_p) : "memory");                                    \
    }                                                                            \
} while (0)

// ---------------------------------------------------------------------------
// Weight precompute: coalesced row-pair reads, scattered frag-order writes.
// Grid: 8 blocks per matrix; block handles 8 row-pairs (1024 (pair,col) items).
// ---------------------------------------------------------------------------
__global__ void wsplit_kernel(const float* __restrict__ Wj,
                              const float* __restrict__ Wi,
                              const float* __restrict__ Wf,
                              const float* __restrict__ rWint,
                              const float* __restrict__ rWatm,
                              const float* __restrict__ rWout,
                              const float* __restrict__ Wg,
                              int n_int, int n_atom, int n_out) {
    int m    = blockIdx.x >> 3;
    int part = blockIdx.x & 7;
    int n_mats = 3 + n_int + n_atom + n_out;

    if (m == n_mats) {  // Wg [32 x 128]: 16 row-pairs x 128 cols = 2048 items
        uint32_t* hi = d_wimg + (size_t)m * 16384;
        uint32_t* lo = hi + 2048;
        if (part >= 1) {
            for (int q = (part - 1) * 256 + threadIdx.x; q < 2048; q += 7 * 256) {
                int p = q >> 7, n = q & 127;
                int k0 = 2 * p;
                float w0 = Wg[k0 * D + n];
                float w1 = Wg[(k0 + 1) * D + n];
                uint32_t h, lw;
                build_frag(w0, w1, h, lw);
                int nt = n >> 3;
                int kt = k0 >> 4;
                int lane = ((n & 7) << 2) + ((k0 >> 1) & 3);
                int ri = (k0 >> 3) & 1;
                int word = ((nt * 2 + kt) * 32 + lane) * 2 + ri;
                hi[word] = h;
                lo[word] = lw;
            }
        }
        return;
    }

    const float* src;
    if (m == 0)                      src = Wj;
    else if (m == 1)                 src = Wi;
    else if (m == 2)                 src = Wf;
    else if (m < 3 + n_int)          src = rWint + (size_t)(m - 3) * D * D;
    else if (m < 3 + n_int + n_atom) src = rWatm + (size_t)(m - 3 - n_int) * D * D;
    else                             src = rWout + (size_t)(m - 3 - n_int - n_atom) * D * D;

    uint32_t* hi = d_wimg + (size_t)m * 16384;
    uint32_t* lo = hi + 8192;

    // 64 row-pairs x 128 cols = 8192 items; this block handles 1024
    for (int q = part * 1024 + threadIdx.x; q < (part + 1) * 1024; q += 256) {
        int p = q >> 7, n = q & 127;
        int k0 = 2 * p;
        float w0 = src[k0 * D + n];          // coalesced across n
        float w1 = src[(k0 + 1) * D + n];    // coalesced across n
        uint32_t h, lw;
        build_frag(w0, w1, h, lw);
        int nt = n >> 3;
        int kt = k0 >> 4;
        int lane = ((n & 7) << 2) + ((k0 >> 1) & 3);
        int ri = (k0 >> 3) & 1;
        int word = ((nt * 8 + kt) * 32 + lane) * 2 + ri;
        hi[word] = h;
        lo[word] = lw;
    }
}

// ---------------------------------------------------------------------------
// MMA stage with B in smem: pass-separated, 4-nt register chunks.
// ---------------------------------------------------------------------------
__device__ __forceinline__ void stage_mma_smem(const uint32_t* wsm, int loff,
                                               const uint32_t* ahi, const uint32_t* alo,
                                               float* acc) {
    const char* base = reinterpret_cast<const char*>(wsm);
    #pragma unroll
    for (int kt = 0; kt < 8; kt++) {
        #pragma unroll
        for (int c = 0; c < 4; c++) {
            uint2 bh[4], bl[4];
            #pragma unroll
            for (int i = 0; i < 4; i++)
                bh[i] = *reinterpret_cast<const uint2*>(base + ((c * 4 + i) * 8 + kt) * 256 + loff);
            #pragma unroll
            for (int i = 0; i < 4; i++)
                bl[i] = *reinterpret_cast<const uint2*>(base + 32768 + ((c * 4 + i) * 8 + kt) * 256 + loff);
            #pragma unroll
            for (int i = 0; i < 4; i++)
                mma_bf16(acc + (c * 4 + i) * 4, ahi + kt * 4, bh[i].x, bh[i].y);
            #pragma unroll
            for (int i = 0; i < 4; i++)
                mma_bf16(acc + (c * 4 + i) * 4, alo + kt * 4, bh[i].x, bh[i].y);
            #pragma unroll
            for (int i = 0; i < 4; i++)
                mma_bf16(acc + (c * 4 + i) * 4, ahi + kt * 4, bl[i].x, bl[i].y);
        }
    }
}

static constexpr int BUFW = 16512;   // words per weight buffer (frags + bias)

__device__ __forceinline__ void issue_stage_copy(uint32_t buf_addr,
                                                 const uint32_t* img,
                                                 const float* bias, int t) {
    #pragma unroll
    for (int i = 0; i < 16; i++)
        CP_ASYNC16(buf_addr + (t + 256 * i) * 16, img + (t + 256 * i) * 4);
    if (t < 32)
        CP_ASYNC16(buf_addr + 16384 * 4 + t * 16, bias + t * 4);
}

// ---------------------------------------------------------------------------
// Head kernel: A = ssp(x); mj = ssp(A@Wj+bj); v = ssp(A@Wi+bi)
// ---------------------------------------------------------------------------
static constexpr int HEAD_SMEM = 2 * BUFW * 4;

__global__ void __launch_bounds__(256, 1)
tc_head_kernel(const float* __restrict__ x,
               const float* __restrict__ bj, const float* __restrict__ bi,
               float* __restrict__ mj, float* __restrict__ v, int N) {
    extern __shared__ uint32_t sm[];
    const uint32_t sm_addr = smem_u32(sm);

    const int t = threadIdx.x, w = t >> 5, l = t & 31;
    const int g = l >> 2, m4 = l & 3;
    const int loff = l * 8;
    const int row_lo = blockIdx.x * 128 + w * 16 + g;
    const int row_hi = row_lo + 8;
    const int cb = 2 * m4;

    issue_stage_copy(sm_addr, d_wimg, bj, t);
    CP_COMMIT();
    issue_stage_copy(sm_addr + BUFW * 4, d_wimg + 16384, bi, t);
    CP_COMMIT();

    uint32_t ahi[32], alo[32];
    #pragma unroll
    for (int nt = 0; nt < 16; nt++) {
        int c0 = nt * 8 + cb;
        float2 a = (row_lo < N) ? *reinterpret_cast<const float2*>(x + (size_t)row_lo * D + c0)
                                : make_float2(0.f, 0.f);
        float2 b = (row_hi < N) ? *reinterpret_cast<const float2*>(x + (size_t)row_hi * D + c0)
                                : make_float2(0.f, 0.f);
        int base = (nt >> 1) * 4 + (nt & 1) * 2;
        build_frag(sspf(a.x), sspf(a.y), ahi[base], alo[base]);
        build_frag(sspf(b.x), sspf(b.y), ahi[base + 1], alo[base + 1]);
    }

    #pragma unroll
    for (int s = 0; s < 2; s++) {
        if (s == 0) CP_WAIT1(); else CP_WAIT0();
        __syncthreads();

        const uint32_t* wbuf = sm + s * BUFW;
        const float* bias_s = reinterpret_cast<const float*>(wbuf + 16384);

        float acc[64];
        #pragma unroll
        for (int i = 0; i < 64; i++) acc[i] = 0.0f;
        stage_mma_smem(wbuf, loff, ahi, alo, acc);

        float* outp = s ? v : mj;
        #pragma unroll
        for (int nt = 0; nt < 16; nt++) {
            int c0 = nt * 8 + cb;
            float bv0 = bias_s[c0], bv1 = bias_s[c0 + 1];
            float s0 = sspf(acc[nt * 4 + 0] + bv0);
            float s1 = sspf(acc[nt * 4 + 1] + bv1);
            float s2 = sspf(acc[nt * 4 + 2] + bv0);
            float s3 = sspf(acc[nt * 4 + 3] + bv1);
            if (row_lo < N)
                *reinterpret_cast<float2*>(outp + (size_t)row_lo * D + c0) = make_float2(s0, s1);
            if (row_hi < N)
                *reinterpret_cast<float2*>(outp + (size_t)row_hi * D + c0) = make_float2(s2, s3);
        }
    }
}

// ---------------------------------------------------------------------------
// Tail kernel: register-chained stages; 3-deep mbarrier weight ring.
// ---------------------------------------------------------------------------
static constexpr int TAIL_SMEM = 3 * BUFW * 4 + 64;

__global__ void __launch_bounds__(256, 1)
tc_tail_kernel(const float* __restrict__ v_in, const float* __restrict__ x,
               const float* __restrict__ u,
               const float* __restrict__ rbint, const float* __restrict__ bf,
               const float* __restrict__ rbatm, const float* __restrict__ rbout,
               int n_int, int n_atom, int n_out,
               float* __restrict__ h_out, float* __restrict__ o_out, int N) {
    extern __shared__ uint32_t sm[];
    const uint32_t sm_addr = smem_u32(sm);
    const uint32_t mb_full  = sm_addr + 3 * BUFW * 4;
    const uint32_t mb_empty = mb_full + 24;

    const int t = threadIdx.x, w = t >> 5, l = t & 31;
    const int g = l >> 2, m4 = l & 3;
    const int loff = l * 8;
    const int row_lo = blockIdx.x * 128 + w * 16 + g;
    const int row_hi = row_lo + 8;
    const int cb = 2 * m4;

    if (t < 3) {
        MBAR_INIT(mb_full + t * 8, 256);
        MBAR_INIT(mb_empty + t * 8, 256);
    }
    __syncthreads();

    const int total = 2 * n_int + 1 + 2 * n_atom + 2 * n_out;

    auto stage_desc = [&](int s, int& mat, const float*& bias, int& mode, bool& storeh) {
        storeh = false;
        if (s < 2 * n_int) {
            mat = 3 + (s >> 1); bias = rbint + (size_t)(s >> 1) * D;
            mode = (s & 1) ? 1 : 0;
        } else if (s == 2 * n_int) {
            mat = 2; bias = bf; mode = 2; storeh = (n_atom == 0);
        } else {
            int s2 = s - 2 * n_int - 1;
            if (s2 < 2 * n_atom) {
                mat = 3 + n_int + (s2 >> 1); bias = rbatm + (size_t)(s2 >> 1) * D;
                mode = (s2 & 1) ? 1 : 0;
                storeh = (s2 == 2 * n_atom - 1);
            } else {
                int s3 = s2 - 2 * n_atom;
                mat = 3 + n_int + n_atom + (s3 >> 1); bias = rbout + (size_t)(s3 >> 1) * D;
                mode = (s3 & 1) ? ((s3 == 2 * n_out - 1) ? 3 : 1) : 0;
            }
        }
    };

    for (int d = 0; d < 2 && d < total; d++) {
        int mat; const float* bias; int mode; bool sh;
        stage_desc(d, mat, bias, mode, sh);
        issue_stage_copy(sm_addr + (uint32_t)d * BUFW * 4,
                         d_wimg + (size_t)mat * 16384, bias, t);
        CP_MBAR_ARRIVE(mb_full + d * 8);
    }

    float vr[64];
    uint32_t ahi[32], alo[32];
    #pragma unroll
    for (int nt = 0; nt < 16; nt++) {
        int c0 = nt * 8 + cb;
        float2 a = (row_lo < N) ? *reinterpret_cast<const float2*>(v_in + (size_t)row_lo * D + c0)
                                : make_float2(0.f, 0.f);
        float2 b = (row_hi < N) ? *reinterpret_cast<const float2*>(v_in + (size_t)row_hi * D + c0)
                                : make_float2(0.f, 0.f);
        vr[nt * 4 + 0] = a.x; vr[nt * 4 + 1] = a.y;
        vr[nt * 4 + 2] = b.x; vr[nt * 4 + 3] = b.y;
        int base = (nt >> 1) * 4 + (nt & 1) * 2;
        build_frag(sspf(a.x), sspf(a.y), ahi[base], alo[base]);
        build_frag(sspf(b.x), sspf(b.y), ahi[base + 1], alo[base + 1]);
    }

    for (int s = 0; s < total; s++) {
        int pf = s + 2;
        if (pf < total) {
            if (pf >= 3)
                MBAR_WAIT(mb_empty + (pf % 3) * 8, ((pf - 3) / 3) & 1);
            int pmat; const float* pbias; int pmode; bool psh;
            stage_desc(pf, pmat, pbias, pmode, psh);
            issue_stage_copy(sm_addr + (uint32_t)(pf % 3) * BUFW * 4,
                             d_wimg + (size_t)pmat * 16384, pbias, t);
            CP_MBAR_ARRIVE(mb_full + (pf % 3) * 8);
        }

        int mat; const float* bias; int mode; bool storeh;
        stage_desc(s, mat, bias, mode, storeh);

        MBAR_WAIT(mb_full + (s % 3) * 8, (s / 3) & 1);

        const uint32_t* wbuf = sm + (s % 3) * BUFW;
        const float* bias_s = reinterpret_cast<const float*>(wbuf + 16384);

        float acc[64];
        #pragma unroll
        for (int i = 0; i < 64; i++) acc[i] = 0.0f;
        stage_mma_smem(wbuf, loff, ahi, alo, acc);

        #pragma unroll
        for (int nt = 0; nt < 16; nt++) {
            int c0 = nt * 8 + cb;
            float bv0 = bias_s[c0], bv1 = bias_s[c0 + 1];
            float v0 = acc[nt * 4 + 0] + bv0;
            float v1 = acc[nt * 4 + 1] + bv1;
            float v2 = acc[nt * 4 + 2] + bv0;
            float v3 = acc[nt * 4 + 3] + bv1;
            if (mode == 1 || mode == 3) {
                v0 += vr[nt * 4 + 0]; v1 += vr[nt * 4 + 1];
                v2 += vr[nt * 4 + 2]; v3 += vr[nt * 4 + 3];
            }
            if (mode == 2) {
                float2 xl = (row_lo < N) ? *reinterpret_cast<const float2*>(x + (size_t)row_lo * D + c0)
                                         : make_float2(0.f, 0.f);
                float2 xh = (row_hi < N) ? *reinterpret_cast<const float2*>(x + (size_t)row_hi * D + c0)
                                         : make_float2(0.f, 0.f);
                float2 uv = __ldg(reinterpret_cast<const float2*>(u + c0));
                v0 += uv.x * sspf(xl.x); v1 += uv.y * sspf(xl.y);
                v2 += uv.x * sspf(xh.x); v3 += uv.y * sspf(xh.y);
            }
            if (mode == 1 || mode == 2) {
                vr[nt * 4 + 0] = v0; vr[nt * 4 + 1] = v1;
                vr[nt * 4 + 2] = v2; vr[nt * 4 + 3] = v3;
            }
            float s0 = sspf(v0), s1 = sspf(v1), s2 = sspf(v2), s3 = sspf(v3);
            if (mode == 3) {
                if (row_lo < N)
                    *reinterpret_cast<float2*>(o_out + (size_t)row_lo * D + c0) = make_float2(s0, s1);
                if (row_hi < N)
                    *reinterpret_cast<float2*>(o_out + (size_t)row_hi * D + c0) = make_float2(s2, s3);
            } else {
                int base = (nt >> 1) * 4 + (nt & 1) * 2;
                build_frag(s0, s1, ahi[base], alo[base]);
                build_frag(s2, s3, ahi[base + 1], alo[base + 1]);
            }
        }

        MBAR_ARRIVE(mb_empty + (s % 3) * 8);

        if (storeh) {
            #pragma unroll
            for (int nt = 0; nt < 16; nt++) {
                int c0 = nt * 8 + cb;
                if (row_lo < N)
                    *reinterpret_cast<float2*>(h_out + (size_t)row_lo * D + c0) =
                        make_float2(vr[nt * 4 + 0], vr[nt * 4 + 1]);
                if (row_hi < N)
                    *reinterpret_cast<float2*>(h_out + (size_t)row_hi * D + c0) =
                        make_float2(vr[nt * 4 + 2], vr[nt * 4 + 3]);
            }
        }
    }
}

// ---------------------------------------------------------------------------
// Edge kernel: HMMA gate + row-major phases; truly persistent grid (296 = one
// full residency wave); unrolled scatter for MLP-16 mj gathers.
// ---------------------------------------------------------------------------
static constexpr int EDGE_SMEM = (4096 + 8 * 16 * 132) * 4;   // 84 KB

__device__ __forceinline__ void edge_scatter_one(const float* __restrict__ stag,
                                                 const float* __restrict__ mj,
                                                 float* __restrict__ v,
                                                 int r, int iv, int jv, int l) {
    int j = __shfl_sync(0xffffffffu, jv, r);
    int i = __shfl_sync(0xffffffffu, iv, r);
    float4 gt = *reinterpret_cast<const float4*>(stag + r * 132 + l * 4);
    float4 m  = __ldg(reinterpret_cast<const float4*>(mj + (size_t)j * D + l * 4));
    float x0 = gt.x * m.x, x1 = gt.y * m.y, x2 = gt.z * m.z, x3 = gt.w * m.w;
    asm volatile("red.global.add.v4.f32 [%0], {%1, %2, %3, %4};"
                 :: "l"(v + (size_t)i * D + l * 4),
                    "f"(x0), "f"(x1), "f"(x2), "f"(x3) : "memory");
}

__global__ void __launch_bounds__(256)
edge_mma_kernel(const float* __restrict__ g,
                const int* __restrict__ idx_i,
                const int* __restrict__ idx_j,
                const float* __restrict__ mj,
                float* __restrict__ v,
                int E, int wg_slot) {
    extern __shared__ uint32_t esm[];
    uint32_t* wgs = esm;                                  // 4096 words
    float* stag_all = reinterpret_cast<float*>(esm + 4096);

    {
        const uint4* src = reinterpret_cast<const uint4*>(d_wimg + (size_t)wg_slot * 16384);
        uint4* dst = reinterpret_cast<uint4*>(wgs);
        #pragma unroll
        for (int i = threadIdx.x; i < 1024; i += 256)
            dst[i] = src[i];
    }
    __syncthreads();

    const int t = threadIdx.x, l = t & 31, w = t >> 5;
    const int gq = l >> 2, m4 = l & 3;
    float* stag = stag_all + w * 16 * 132;
    const char* base = reinterpret_cast<const char*>(wgs);
    const int loff = l * 8;

    const int nbatches = (E + 15) / 16;
    for (int batch = blockIdx.x * 8 + w; batch < nbatches; batch += gridDim.x * 8) {
        const int e0 = batch * 16;
        const int nb = min(16, E - e0);

        int iv = 0, jv = 0;
        if (l < nb) { iv = __ldg(idx_i + e0 + l); jv = __ldg(idx_j + e0 + l); }

        #pragma unroll
        for (int rr = 0; rr < 4; rr++) {
            int r = rr * 4 + (l >> 3);
            if (r < nb) {
                float4 gv = *reinterpret_cast<const float4*>(g + (size_t)(e0 + r) * 32 + (l & 7) * 4);
                *reinterpret_cast<float4*>(stag + r * 132 + (l & 7) * 4) = gv;
            }
        }
        __syncwarp();

        uint32_t ahi[8], alo[8];
        #pragma unroll
        for (int kt = 0; kt < 2; kt++) {
            int kb = kt * 16 + 2 * m4;
            float2 p00 = (gq < nb)     ? *reinterpret_cast<const float2*>(stag + gq * 132 + kb)
                                       : make_float2(0.f, 0.f);
            float2 p01 = (gq < nb)     ? *reinterpret_cast<const float2*>(stag + gq * 132 + kb + 8)
                                       : make_float2(0.f, 0.f);
            float2 p10 = (8 + gq < nb) ? *reinterpret_cast<const float2*>(stag + (8 + gq) * 132 + kb)
                                       : make_float2(0.f, 0.f);
            float2 p11 = (8 + gq < nb) ? *reinterpret_cast<const float2*>(stag + (8 + gq) * 132 + kb + 8)
                                       : make_float2(0.f, 0.f);
            build_frag(p00.x, p00.y, ahi[kt * 4 + 0], alo[kt * 4 + 0]);
            build_frag(p10.x, p10.y, ahi[kt * 4 + 1], alo[kt * 4 + 1]);
            build_frag(p01.x, p01.y, ahi[kt * 4 + 2], alo[kt * 4 + 2]);
            build_frag(p11.x, p11.y, ahi[kt * 4 + 3], alo[kt * 4 + 3]);
        }
        __syncwarp();

        float acc[64];
        #pragma unroll
        for (int i = 0; i < 64; i++) acc[i] = 0.0f;

        #pragma unroll
        for (int nt = 0; nt < 16; nt++) {
            #pragma unroll
            for (int kt = 0; kt < 2; kt++) {
                uint2 bh = *reinterpret_cast<const uint2*>(base + (nt * 2 + kt) * 256 + loff);
                mma_bf16(acc + nt * 4, ahi + kt * 4, bh.x, bh.y);
                mma_bf16(acc + nt * 4, alo + kt * 4, bh.x, bh.y);
                uint2 bl = *reinterpret_cast<const uint2*>(base + 8192 + (nt * 2 + kt) * 256 + loff);
                mma_bf16(acc + nt * 4, ahi + kt * 4, bl.x, bl.y);
            }
        }

        #pragma unroll
        for (int nt = 0; nt < 16; nt++) {
            int c0 = nt * 8 + 2 * m4;
            if (gq < nb)
                *reinterpret_cast<float2*>(stag + gq * 132 + c0) =
                    make_float2(acc[nt * 4 + 0], acc[nt * 4 + 1]);
            if (8 + gq < nb)
                *reinterpret_cast<float2*>(stag + (8 + gq) * 132 + c0) =
                    make_float2(acc[nt * 4 + 2], acc[nt * 4 + 3]);
        }
        __syncwarp();

        if (nb == 16) {
            #pragma unroll
            for (int r = 0; r < 16; r++)
                edge_scatter_one(stag, mj, v, r, iv, jv, l);
        } else {
            for (int r = 0; r < nb; r++)
                edge_scatter_one(stag, mj, v, r, iv, jv, l);
        }
        __syncwarp();
    }
}

// ---------------------------------------------------------------------------
// Host-side dispatch
// ---------------------------------------------------------------------------
extern "C" void kernel_launch(void* const* d_in, const int* in_sizes, int n_in,
                              void* d_out, int out_size) {
    const float* x     = (const float*)d_in[0];
    const float* g_ij  = (const float*)d_in[1];
    const float* Wf    = (const float*)d_in[2];
    const float* bf    = (const float*)d_in[3];
    const float* Wg    = (const float*)d_in[4];
    const float* Wj    = (const float*)d_in[5];
    const float* bj    = (const float*)d_in[6];
    const float* Wi    = (const float*)d_in[7];
    const float* bi    = (const float*)d_in[8];
    const float* u     = (const float*)d_in[9];
    const float* rWint = (const float*)d_in[10];
    const float* rbint = (const float*)d_in[11];
    const float* rWatm = (const float*)d_in[12];
    const float* rbatm = (const float*)d_in[13];
    const float* rWout = (const float*)d_in[14];
    const float* rbout = (const float*)d_in[15];
    const int*   idx_i = (const int*)d_in[16];
    const int*   idx_j = (const int*)d_in[17];

    const int N      = in_sizes[0] / D;
    const int E      = in_sizes[16];
    const int n_int  = in_sizes[11] / D;
    const int n_atom = in_sizes[13] / D;
    const int n_out  = in_sizes[15] / D;

    if (N > MAXN) return;
    const int n_mats = 3 + n_int + n_atom + n_out;
    if (n_mats + 1 > MAXMATS) return;

    float *mj, *v;
    cudaGetSymbolAddress((void**)&mj, d_mj);
    cudaGetSymbolAddress((void**)&v,  d_v);

    float* o_out = (float*)d_out;                 // o -> first N*D
    float* h_out = (float*)d_out + (size_t)N * D; // h -> second N*D

    cudaFuncSetAttribute(tc_head_kernel, cudaFuncAttributeMaxDynamicSharedMemorySize, HEAD_SMEM);
    cudaFuncSetAttribute(tc_tail_kernel, cudaFuncAttributeMaxDynamicSharedMemorySize, TAIL_SMEM);
    cudaFuncSetAttribute(edge_mma_kernel, cudaFuncAttributeMaxDynamicSharedMemorySize, EDGE_SMEM);

    const int tiles = (N + 127) / 128;

    // 0) split + permute weights (coalesced reads; Wg at slot n_mats)
    wsplit_kernel<<<(n_mats + 1) * 8, 256>>>(Wj, Wi, Wf, rWint, rWatm, rWout, Wg,
                                             n_int, n_atom, n_out);

    // 1) mj = ssp(ssp(x)@Wj+bj); v = ssp(ssp(x)@Wi+bi)
    tc_head_kernel<<<tiles, 256, HEAD_SMEM>>>(x, bj, bi, mj, v, N);

    // 2) v += segment_sum( (g_ij @ Wg) * mj[idx_j], idx_i )
    {
        int batches = (E + 15) / 16;
        int blocks  = (batches + 7) / 8;
        if (blocks > 296) blocks = 296;   // 2 CTAs/SM residency -> one wave
        edge_mma_kernel<<<blocks, 256, EDGE_SMEM>>>(g_ij, idx_i, idx_j, mj, v, E, n_mats);
    }

    // 3) fused tail with mbarrier weight ring
    tc_tail_kernel<<<tiles, 256, TAIL_SMEM>>>(
        v, x, u, rbint, bf, rbatm, rbout, n_int, n_atom, n_out, h_out, o_out, N);
}